// round 8
// baseline (speedup 1.0000x reference)
#include <cuda_runtime.h>
#include <cuda_bf16.h>
#include <math.h>
#include <cstdint>

// ---------------------------------------------------------------------------
// SpectroTFDecoder: pre-LN transformer decoder layer, fp32 I/O.
// GEMMs: mma.sync bf16 tensor cores, hi/lo split (3-MMA compensation),
// cp.async 3-stage pipeline, CTA tile 128x64 with 2 CTAs/SM for latency hiding.
// Attention/LN SIMT fp32; splits fused into producers.
// Input order: 0 x, 1 src_x, 2 mask, 3 src_mask, 4-9 ln{1,2,3}_{g,b},
// 10-17 weights (sa_wq,sa_wk,sa_wv,sa_wo,ca_wq,ca_wk,ca_wv,ca_wo),
// 18-25 biases (same order), 26-29 ff_w1,ff_b1,ff_w2,ff_b2.
// ---------------------------------------------------------------------------

#define D_MODEL 1024
#define BATCH   4
#define TSEQ    1024
#define N_ROWS  (BATCH * TSEQ)
#define NHEAD   16
#define DHEAD   64
#define DFF_    4096
#define LN_EPS  1e-6f

// fp32 scratch
__device__ float g_q  [N_ROWS * D_MODEL];
__device__ float g_k  [N_ROWS * D_MODEL];
__device__ float g_v  [N_ROWS * D_MODEL];
__device__ float g_x1 [N_ROWS * D_MODEL];
__device__ float g_x2 [N_ROWS * D_MODEL];

// bf16 hi/lo scratch
#define WQ_OFF  0
#define WK_OFF  (1 << 20)
#define WV_OFF  (2 << 20)
#define WO_OFF  (3 << 20)
#define CQ_OFF  (4 << 20)
#define CK_OFF  (5 << 20)
#define CV_OFF  (6 << 20)
#define CO_OFF  (7 << 20)
#define W1_OFF  (8 << 20)
#define W2_OFF  (12 << 20)
__device__ __nv_bfloat16 g_whi[16 << 20];   // weights (transposed [N,K])
__device__ __nv_bfloat16 g_wlo[16 << 20];
__device__ __nv_bfloat16 g_ahi[4 << 20];    // activation split (D-wide)
__device__ __nv_bfloat16 g_alo[4 << 20];
__device__ __nv_bfloat16 g_shi[4 << 20];    // src_x split (persistent)
__device__ __nv_bfloat16 g_slo[4 << 20];
__device__ __nv_bfloat16 g_fhi[16 << 20];   // FF intermediate split
__device__ __nv_bfloat16 g_flo[16 << 20];

// ---------------------------------------------------------------------------
// asm helpers
// ---------------------------------------------------------------------------
__device__ __forceinline__ uint32_t smem_u32(const void* p) {
    uint32_t a;
    asm("{ .reg .u64 t; cvta.to.shared.u64 t, %1; cvt.u32.u64 %0, t; }"
        : "=r"(a) : "l"(p));
    return a;
}
__device__ __forceinline__ void ldm4(uint32_t* r, uint32_t a) {
    asm volatile("ldmatrix.sync.aligned.m8n8.x4.shared.b16 {%0,%1,%2,%3}, [%4];"
                 : "=r"(r[0]), "=r"(r[1]), "=r"(r[2]), "=r"(r[3]) : "r"(a));
}
__device__ __forceinline__ void mma16816(float* c, const uint32_t* a,
                                         const uint32_t* b) {
    asm volatile(
        "mma.sync.aligned.m16n8k16.row.col.f32.bf16.bf16.f32 "
        "{%0,%1,%2,%3},{%4,%5,%6,%7},{%8,%9},{%0,%1,%2,%3};"
        : "+f"(c[0]), "+f"(c[1]), "+f"(c[2]), "+f"(c[3])
        : "r"(a[0]), "r"(a[1]), "r"(a[2]), "r"(a[3]), "r"(b[0]), "r"(b[1]));
}
#define CPA16(dst, src) \
    asm volatile("cp.async.cg.shared.global [%0], [%1], 16;" :: "r"(dst), "l"(src))
#define CPA_COMMIT() asm volatile("cp.async.commit_group;" ::: "memory")
#define CPA_WAIT1()  asm volatile("cp.async.wait_group 1;"  ::: "memory")

__device__ __forceinline__ void split1(float a, __nv_bfloat16& h, __nv_bfloat16& l) {
    h = __float2bfloat16(a);
    l = __float2bfloat16(a - __bfloat162float(h));
}

// ---------------------------------------------------------------------------
// split: fp32 -> bf16 hi + lo. n multiple of 1024.
// ---------------------------------------------------------------------------
__global__ __launch_bounds__(256)
void split_kernel(const float* __restrict__ in, __nv_bfloat16* __restrict__ hi,
                  __nv_bfloat16* __restrict__ lo)
{
    const int i = (blockIdx.x * 256 + threadIdx.x) * 4;
    float4 a = *(const float4*)(in + i);
    float av[4] = {a.x, a.y, a.z, a.w};
    __nv_bfloat16 hv[4], lv[4];
    #pragma unroll
    for (int j = 0; j < 4; j++) split1(av[j], hv[j], lv[j]);
    __nv_bfloat162 h01{hv[0], hv[1]}, h23{hv[2], hv[3]};
    __nv_bfloat162 l01{lv[0], lv[1]}, l23{lv[2], lv[3]};
    *(__nv_bfloat162*)(hi + i)     = h01;
    *(__nv_bfloat162*)(hi + i + 2) = h23;
    *(__nv_bfloat162*)(lo + i)     = l01;
    *(__nv_bfloat162*)(lo + i + 2) = l23;
}

// ---------------------------------------------------------------------------
// transpose + split: W[K,N] fp32 -> out[N,K] bf16 hi/lo.
// ---------------------------------------------------------------------------
__global__ __launch_bounds__(256)
void tsplit_kernel(const float* __restrict__ W, __nv_bfloat16* __restrict__ hi,
                   __nv_bfloat16* __restrict__ lo, int K, int N)
{
    __shared__ float t[32][33];
    const int x = threadIdx.x & 31;
    const int y = threadIdx.x >> 5;
    const int k0 = blockIdx.y * 32;
    const int n0 = blockIdx.x * 32;
    #pragma unroll
    for (int r = y; r < 32; r += 8)
        t[r][x] = W[(size_t)(k0 + r) * N + n0 + x];
    __syncthreads();
    #pragma unroll
    for (int r = y; r < 32; r += 8) {
        float a = t[x][r];
        __nv_bfloat16 h, l;
        split1(a, h, l);
        const size_t o = (size_t)(n0 + r) * K + k0 + x;
        hi[o] = h;
        lo[o] = l;
    }
}

// ---------------------------------------------------------------------------
// LayerNorm fused with hi/lo split output.
// ---------------------------------------------------------------------------
__global__ __launch_bounds__(256)
void ln_split_kernel(const float* __restrict__ x, const float* __restrict__ g,
                     const float* __restrict__ bta,
                     __nv_bfloat16* __restrict__ hi, __nv_bfloat16* __restrict__ lo)
{
    const int row = blockIdx.x;
    const int t = threadIdx.x;
    const float* xr = x + (size_t)row * D_MODEL;
    float4 xv = *(const float4*)(xr + t * 4);

    float s = xv.x + xv.y + xv.z + xv.w;
    __shared__ float red[8];
    #pragma unroll
    for (int off = 16; off > 0; off >>= 1) s += __shfl_xor_sync(~0u, s, off);
    if ((t & 31) == 0) red[t >> 5] = s;
    __syncthreads();
    float tot = 0.f;
    #pragma unroll
    for (int i = 0; i < 8; i++) tot += red[i];
    const float mu = tot * (1.f / 1024.f);

    const float dx0 = xv.x - mu, dx1 = xv.y - mu, dx2 = xv.z - mu, dx3 = xv.w - mu;
    float sq = dx0*dx0 + dx1*dx1 + dx2*dx2 + dx3*dx3;
    #pragma unroll
    for (int off = 16; off > 0; off >>= 1) sq += __shfl_xor_sync(~0u, sq, off);
    __syncthreads();
    if ((t & 31) == 0) red[t >> 5] = sq;
    __syncthreads();
    float tot2 = 0.f;
    #pragma unroll
    for (int i = 0; i < 8; i++) tot2 += red[i];
    const float sigma = sqrtf(tot2 * (1.f / 1024.f));
    const float inv = 1.f / (sigma + LN_EPS);

    float4 gv = *(const float4*)(g + t * 4);
    float4 bv = *(const float4*)(bta + t * 4);
    float o0 = dx0 * inv * gv.x + bv.x;
    float o1 = dx1 * inv * gv.y + bv.y;
    float o2 = dx2 * inv * gv.z + bv.z;
    float o3 = dx3 * inv * gv.w + bv.w;

    __nv_bfloat16 h0,h1,h2,h3,l0,l1,l2,l3;
    split1(o0,h0,l0); split1(o1,h1,l1); split1(o2,h2,l2); split1(o3,h3,l3);
    const size_t o = (size_t)row * D_MODEL + t * 4;
    __nv_bfloat162 ha{h0,h1}, hb{h2,h3}, la{l0,l1}, lb{l2,l3};
    *(__nv_bfloat162*)(hi + o)     = ha;
    *(__nv_bfloat162*)(hi + o + 2) = hb;
    *(__nv_bfloat162*)(lo + o)     = la;
    *(__nv_bfloat162*)(lo + o + 2) = lb;
}

// ---------------------------------------------------------------------------
// Tensor-core GEMM, CTA tile 128x64, BK=32, cp.async 3-stage, 2 CTAs/SM.
// C[M,N] = A@W + bias (+res), optional ReLU, optional split-bf16 output.
// A split [M,K] row-major; B = W^T split [N,K] row-major.
// 8 warps as 4(M) x 2(N); warp tile 32x32; 3-MMA hi/lo compensation.
// SMEM stage: Ahi/Alo 128x40, Bhi/Blo 64x40 (bf16, padded rows).
// ---------------------------------------------------------------------------
#define TG_ROW  40                        // padded row stride (bf16 elems)
#define TG_AB   (128 * TG_ROW * 2)        // A tile bytes: 10240
#define TG_BB   (64 * TG_ROW * 2)         // B tile bytes: 5120
#define TG_BOFF (2 * TG_AB)               // offset of Bhi within stage
#define TG_STAGE (2 * TG_AB + 2 * TG_BB)  // 30720
#define TC_SMEM (3 * TG_STAGE)            // 92160

template<bool RELU, bool RES, bool SPLITOUT>
__global__ __launch_bounds__(256, 2)
void tc_gemm(const __nv_bfloat16* __restrict__ Ahi, const __nv_bfloat16* __restrict__ Alo,
             const __nv_bfloat16* __restrict__ Bhi, const __nv_bfloat16* __restrict__ Blo,
             const float* __restrict__ bias, const float* __restrict__ res,
             float* __restrict__ C,
             __nv_bfloat16* __restrict__ Chi, __nv_bfloat16* __restrict__ Clo,
             int M, int N, int K)
{
    extern __shared__ __align__(128) char dynsmem[];
    const uint32_t sb = smem_u32(dynsmem);
    const int tid = threadIdx.x;
    const int lane = tid & 31;
    const int wid = tid >> 5;
    const int wm = wid >> 1;          // 0..3  (M)
    const int wn = wid & 1;           // 0..1  (N)
    const int bm = blockIdx.y * 128;
    const int bn = blockIdx.x * 64;

    // A staging: thread -> (row 0..127, 16-elem half)
    const int sarow = tid >> 1;
    const int sahalf = (tid & 1) * 16;
    const uint32_t sao = (uint32_t)(sarow * TG_ROW + sahalf) * 2;
    // B staging: thread -> (row 0..63, 8-elem quarter)
    const int sbrow = tid >> 2;
    const int sbq = (tid & 3) * 8;
    const uint32_t sbo = (uint32_t)(sbrow * TG_ROW + sbq) * 2;

    const char* gAh = (const char*)(Ahi + (size_t)(bm + sarow) * K + sahalf);
    const char* gAl = (const char*)(Alo + (size_t)(bm + sarow) * K + sahalf);
    const char* gBh = (const char*)(Bhi + (size_t)(bn + sbrow) * K + sbq);
    const char* gBl = (const char*)(Blo + (size_t)(bn + sbrow) * K + sbq);

    // ldmatrix offsets within a stage
    const uint32_t a_off = (uint32_t)((lane & 15) * TG_ROW * 2 + (lane >> 4) * 16);
    const uint32_t b_off = (uint32_t)((((lane >> 4) << 3) + (lane & 7)) * TG_ROW * 2
                                      + ((lane >> 3) & 1) * 16);
    uint32_t aAddr[2], bAddr[2];
    #pragma unroll
    for (int mt = 0; mt < 2; mt++)
        aAddr[mt] = sb + (uint32_t)((wm * 32 + mt * 16) * TG_ROW * 2) + a_off;
    #pragma unroll
    for (int ng = 0; ng < 2; ng++)
        bAddr[ng] = sb + TG_BOFF + (uint32_t)((wn * 32 + ng * 16) * TG_ROW * 2) + b_off;

    float acc[2][4][4];
    #pragma unroll
    for (int mt = 0; mt < 2; mt++)
        #pragma unroll
        for (int nt = 0; nt < 4; nt++)
            #pragma unroll
            for (int r = 0; r < 4; r++) acc[mt][nt][r] = 0.f;

    const int nk = K >> 5;     // BK = 32

    auto issue = [&](int s, int kt) {
        const uint32_t tb = sb + (uint32_t)s * TG_STAGE;
        const int gb = kt * 64;     // 32 elems * 2B
        CPA16(tb + sao,                 gAh + gb);
        CPA16(tb + sao + 16,            gAh + gb + 16);
        CPA16(tb + TG_AB + sao,         gAl + gb);
        CPA16(tb + TG_AB + sao + 16,    gAl + gb + 16);
        CPA16(tb + TG_BOFF + sbo,         gBh + gb);
        CPA16(tb + TG_BOFF + TG_BB + sbo, gBl + gb);
    };

    issue(0, 0); CPA_COMMIT();
    issue(1, 1); CPA_COMMIT();

    int cs = 0;
    for (int kt = 0; kt < nk; kt++) {
        CPA_WAIT1();
        __syncthreads();
        if (kt + 2 < nk) {
            int is = cs + 2; if (is >= 3) is -= 3;
            issue(is, kt + 2);
        }
        CPA_COMMIT();

        const uint32_t stg = (uint32_t)cs * TG_STAGE;
        #pragma unroll
        for (int ks = 0; ks < 2; ks++) {
            const uint32_t kb = stg + ks * 32;
            uint32_t ah[2][4], al[2][4], bh[2][4], bl[2][4];
            #pragma unroll
            for (int mt = 0; mt < 2; mt++) {
                ldm4(ah[mt], aAddr[mt] + kb);
                ldm4(al[mt], aAddr[mt] + TG_AB + kb);
            }
            #pragma unroll
            for (int ng = 0; ng < 2; ng++) {
                ldm4(bh[ng], bAddr[ng] + kb);
                ldm4(bl[ng], bAddr[ng] + TG_BB + kb);
            }
            #pragma unroll
            for (int mt = 0; mt < 2; mt++) {
                #pragma unroll
                for (int nt = 0; nt < 4; nt++) {
                    const int ng = nt >> 1;
                    const int hf = (nt & 1) * 2;
                    mma16816(acc[mt][nt], ah[mt], &bh[ng][hf]);
                    mma16816(acc[mt][nt], ah[mt], &bl[ng][hf]);
                    mma16816(acc[mt][nt], al[mt], &bh[ng][hf]);
                }
            }
        }
        cs++; if (cs == 3) cs = 0;
    }

    // epilogue
    const int er = lane >> 2;
    const int ec = (lane & 3) * 2;
    #pragma unroll
    for (int mt = 0; mt < 2; mt++) {
        const int row0 = bm + wm * 32 + mt * 16 + er;
        #pragma unroll
        for (int nt = 0; nt < 4; nt++) {
            const int col = bn + wn * 32 + nt * 8 + ec;
            float2 bv = *(const float2*)(bias + col);
            float v0 = acc[mt][nt][0] + bv.x;
            float v1 = acc[mt][nt][1] + bv.y;
            float v2 = acc[mt][nt][2] + bv.x;
            float v3 = acc[mt][nt][3] + bv.y;
            if (RELU) {
                v0 = fmaxf(v0, 0.f); v1 = fmaxf(v1, 0.f);
                v2 = fmaxf(v2, 0.f); v3 = fmaxf(v3, 0.f);
            }
            if (RES) {
                float2 r0 = *(const float2*)(res + (size_t)row0 * N + col);
                float2 r1 = *(const float2*)(res + (size_t)(row0 + 8) * N + col);
                v0 += r0.x; v1 += r0.y; v2 += r1.x; v3 += r1.y;
            }
            if (SPLITOUT) {
                __nv_bfloat16 h0,h1,h2,h3,l0,l1,l2,l3;
                split1(v0,h0,l0); split1(v1,h1,l1);
                split1(v2,h2,l2); split1(v3,h3,l3);
                __nv_bfloat162 ha{h0,h1}, hb{h2,h3}, la{l0,l1}, lb{l2,l3};
                *(__nv_bfloat162*)(Chi + (size_t)row0 * N + col)       = ha;
                *(__nv_bfloat162*)(Chi + (size_t)(row0 + 8) * N + col) = hb;
                *(__nv_bfloat162*)(Clo + (size_t)row0 * N + col)       = la;
                *(__nv_bfloat162*)(Clo + (size_t)(row0 + 8) * N + col) = lb;
            } else {
                float2 o0 = {v0, v1};
                float2 o1 = {v2, v3};
                *(float2*)(C + (size_t)row0 * N + col) = o0;
                *(float2*)(C + (size_t)(row0 + 8) * N + col) = o1;
            }
        }
    }
}

// ---------------------------------------------------------------------------
// Flash attention (register-tiled), epilogue writes bf16 hi/lo split.
// ---------------------------------------------------------------------------
#define AST 68
#define ATTN_SMEM (4 * 64 * AST * (int)sizeof(float))

__global__ __launch_bounds__(256)
void attn_kernel(const float* __restrict__ Q, const float* __restrict__ Kv,
                 const float* __restrict__ Vv,
                 __nv_bfloat16* __restrict__ Ohi, __nv_bfloat16* __restrict__ Olo,
                 int causal)
{
    const int qt = blockIdx.x;
    const int h  = blockIdx.y;
    const int b  = blockIdx.z;
    const int tid = threadIdx.x;
    const int ty = tid >> 4;
    const int tx = tid & 15;

    const size_t base = ((size_t)b * TSEQ) * D_MODEL + (size_t)h * DHEAD;

    extern __shared__ __align__(128) char dynsmem[];
    float* sm = (float*)dynsmem;
    float* Qt = sm;
    float* Kt = sm + 64 * AST;
    float* Vs = sm + 2 * 64 * AST;
    float* Pt = sm + 3 * 64 * AST;

    const int r  = tid >> 2;
    const int cc = (tid & 3) * 16;

    {
        const float* src = Q + base + (size_t)(qt * 64 + r) * D_MODEL + cc;
        #pragma unroll
        for (int c = 0; c < 16; c += 4) {
            float4 v4 = *(const float4*)(src + c);
            Qt[(cc + c + 0) * AST + r] = v4.x * 0.125f;
            Qt[(cc + c + 1) * AST + r] = v4.y * 0.125f;
            Qt[(cc + c + 2) * AST + r] = v4.z * 0.125f;
            Qt[(cc + c + 3) * AST + r] = v4.w * 0.125f;
        }
    }

    float m[4], l[4], acc[4][4];
    #pragma unroll
    for (int i = 0; i < 4; i++) {
        m[i] = -INFINITY; l[i] = 0.f;
        #pragma unroll
        for (int j = 0; j < 4; j++) acc[i][j] = 0.f;
    }

    const int ktEnd = causal ? qt : (TSEQ / 64 - 1);

    for (int kt = 0; kt <= ktEnd; kt++) {
        __syncthreads();
        {
            const float* ks = Kv + base + (size_t)(kt * 64 + r) * D_MODEL + cc;
            const float* vs = Vv + base + (size_t)(kt * 64 + r) * D_MODEL + cc;
            #pragma unroll
            for (int c = 0; c < 16; c += 4) {
                float4 k4 = *(const float4*)(ks + c);
                Kt[(cc + c + 0) * AST + r] = k4.x;
                Kt[(cc + c + 1) * AST + r] = k4.y;
                Kt[(cc + c + 2) * AST + r] = k4.z;
                Kt[(cc + c + 3) * AST + r] = k4.w;
                float4 v4 = *(const float4*)(vs + c);
                *(float4*)&Vs[r * AST + cc + c] = v4;
            }
        }
        __syncthreads();

        float s[4][4];
        #pragma unroll
        for (int i = 0; i < 4; i++)
            #pragma unroll
            for (int j = 0; j < 4; j++) s[i][j] = 0.f;
        #pragma unroll 4
        for (int dd = 0; dd < 64; dd++) {
            float4 q4 = *(const float4*)&Qt[dd * AST + 4 * ty];
            float4 k4 = *(const float4*)&Kt[dd * AST + 4 * tx];
            float qa[4] = {q4.x, q4.y, q4.z, q4.w};
            float ka[4] = {k4.x, k4.y, k4.z, k4.w};
            #pragma unroll
            for (int i = 0; i < 4; i++)
                #pragma unroll
                for (int j = 0; j < 4; j++)
                    s[i][j] += qa[i] * ka[j];
        }

        const bool diag = causal && (kt == qt);
        float p[4][4];
        #pragma unroll
        for (int i = 0; i < 4; i++) {
            const int qg = qt * 64 + 4 * ty + i;
            float rmax = -INFINITY;
            #pragma unroll
            for (int j = 0; j < 4; j++) {
                if (diag && (kt * 64 + 4 * tx + j) > qg) s[i][j] = -INFINITY;
                rmax = fmaxf(rmax, s[i][j]);
            }
            rmax = fmaxf(rmax, __shfl_xor_sync(~0u, rmax, 1));
            rmax = fmaxf(rmax, __shfl_xor_sync(~0u, rmax, 2));
            rmax = fmaxf(rmax, __shfl_xor_sync(~0u, rmax, 4));
            rmax = fmaxf(rmax, __shfl_xor_sync(~0u, rmax, 8));
            const float mnew = fmaxf(m[i], rmax);
            const float corr = __expf(m[i] - mnew);
            float rsum = 0.f;
            #pragma unroll
            for (int j = 0; j < 4; j++) {
                p[i][j] = __expf(s[i][j] - mnew);
                rsum += p[i][j];
            }
            rsum += __shfl_xor_sync(~0u, rsum, 1);
            rsum += __shfl_xor_sync(~0u, rsum, 2);
            rsum += __shfl_xor_sync(~0u, rsum, 4);
            rsum += __shfl_xor_sync(~0u, rsum, 8);
            l[i] = l[i] * corr + rsum;
            m[i] = mnew;
            #pragma unroll
            for (int j = 0; j < 4; j++) acc[i][j] *= corr;
        }

        #pragma unroll
        for (int j = 0; j < 4; j++) {
            float4 pj = {p[0][j], p[1][j], p[2][j], p[3][j]};
            *(float4*)&Pt[(4 * tx + j) * AST + 4 * ty] = pj;
        }
        __syncthreads();

        #pragma unroll 4
        for (int kk = 0; kk < 64; kk++) {
            float4 p4 = *(const float4*)&Pt[kk * AST + 4 * ty];
            float4 v4 = *(const float4*)&Vs[kk * AST + 4 * tx];
            float pa[4] = {p4.x, p4.y, p4.z, p4.w};
            float va[4] = {v4.x, v4.y, v4.z, v4.w};
            #pragma unroll
            for (int i = 0; i < 4; i++)
                #pragma unroll
                for (int j = 0; j < 4; j++)
                    acc[i][j] += pa[i] * va[j];
        }
    }

    #pragma unroll
    for (int i = 0; i < 4; i++) {
        const float inv = 1.f / l[i];
        const size_t o = base + (size_t)(qt * 64 + 4 * ty + i) * D_MODEL + 4 * tx;
        float o0 = acc[i][0] * inv, o1 = acc[i][1] * inv;
        float o2 = acc[i][2] * inv, o3 = acc[i][3] * inv;
        __nv_bfloat16 h0,h1,h2,h3,l0,l1,l2,l3;
        split1(o0,h0,l0); split1(o1,h1,l1); split1(o2,h2,l2); split1(o3,h3,l3);
        __nv_bfloat162 ha{h0,h1}, hb{h2,h3}, la{l0,l1}, lb{l2,l3};
        *(__nv_bfloat162*)(Ohi + o)     = ha;
        *(__nv_bfloat162*)(Ohi + o + 2) = hb;
        *(__nv_bfloat162*)(Olo + o)     = la;
        *(__nv_bfloat162*)(Olo + o + 2) = lb;
    }
}

// ---------------------------------------------------------------------------
// Host orchestration
// ---------------------------------------------------------------------------
extern "C" void kernel_launch(void* const* d_in, const int* in_sizes, int n_in,
                              void* d_out, int out_size)
{
    (void)in_sizes; (void)n_in; (void)out_size;
    const float* x     = (const float*)d_in[0];
    const float* src_x = (const float*)d_in[1];
    const float* ln1_g = (const float*)d_in[4];
    const float* ln1_b = (const float*)d_in[5];
    const float* ln2_g = (const float*)d_in[6];
    const float* ln2_b = (const float*)d_in[7];
    const float* ln3_g = (const float*)d_in[8];
    const float* ln3_b = (const float*)d_in[9];
    const float* W[8];
    for (int i = 0; i < 8; i++) W[i] = (const float*)d_in[10 + i];
    const float* Bv[8];
    for (int i = 0; i < 8; i++) Bv[i] = (const float*)d_in[18 + i];
    const float* ff_w1 = (const float*)d_in[26];
    const float* ff_b1 = (const float*)d_in[27];
    const float* ff_w2 = (const float*)d_in[28];
    const float* ff_b2 = (const float*)d_in[29];
    float* out = (float*)d_out;

    float *q, *k, *v, *x1, *x2;
    cudaGetSymbolAddress((void**)&q,  g_q);
    cudaGetSymbolAddress((void**)&k,  g_k);
    cudaGetSymbolAddress((void**)&v,  g_v);
    cudaGetSymbolAddress((void**)&x1, g_x1);
    cudaGetSymbolAddress((void**)&x2, g_x2);
    __nv_bfloat16 *whi, *wlo, *ahi, *alo, *shi, *slo, *fhi, *flo;
    cudaGetSymbolAddress((void**)&whi, g_whi);
    cudaGetSymbolAddress((void**)&wlo, g_wlo);
    cudaGetSymbolAddress((void**)&ahi, g_ahi);
    cudaGetSymbolAddress((void**)&alo, g_alo);
    cudaGetSymbolAddress((void**)&shi, g_shi);
    cudaGetSymbolAddress((void**)&slo, g_slo);
    cudaGetSymbolAddress((void**)&fhi, g_fhi);
    cudaGetSymbolAddress((void**)&flo, g_flo);

    cudaFuncSetAttribute(attn_kernel,
                         cudaFuncAttributeMaxDynamicSharedMemorySize, ATTN_SMEM);
    cudaFuncSetAttribute(tc_gemm<false, false, false>,
                         cudaFuncAttributeMaxDynamicSharedMemorySize, TC_SMEM);
    cudaFuncSetAttribute(tc_gemm<false, true, false>,
                         cudaFuncAttributeMaxDynamicSharedMemorySize, TC_SMEM);
    cudaFuncSetAttribute(tc_gemm<true, false, true>,
                         cudaFuncAttributeMaxDynamicSharedMemorySize, TC_SMEM);

    const dim3 gD (D_MODEL / 64, N_ROWS / 128);    // (16, 32)
    const dim3 gF1(DFF_   / 64, N_ROWS / 128);     // (64, 32)
    const dim3 gAtt(TSEQ / 64, NHEAD, BATCH);
    const dim3 gsq(D_MODEL / 32, D_MODEL / 32);

    // ---- launches 0-4: sa weight prep + ln1 ----
    tsplit_kernel<<<gsq, 256>>>(W[0], whi + WQ_OFF, wlo + WQ_OFF, D_MODEL, D_MODEL);
    tsplit_kernel<<<gsq, 256>>>(W[1], whi + WK_OFF, wlo + WK_OFF, D_MODEL, D_MODEL);
    tsplit_kernel<<<gsq, 256>>>(W[2], whi + WV_OFF, wlo + WV_OFF, D_MODEL, D_MODEL);
    tsplit_kernel<<<gsq, 256>>>(W[3], whi + WO_OFF, wlo + WO_OFF, D_MODEL, D_MODEL);
    ln_split_kernel<<<N_ROWS, 256>>>(x, ln1_g, ln1_b, ahi, alo);

    // ---- self-attention block ----
    tc_gemm<false, false, false><<<gD, 256, TC_SMEM>>>(ahi, alo, whi + WQ_OFF, wlo + WQ_OFF, Bv[0], nullptr, q, nullptr, nullptr, N_ROWS, D_MODEL, D_MODEL);
    tc_gemm<false, false, false><<<gD, 256, TC_SMEM>>>(ahi, alo, whi + WK_OFF, wlo + WK_OFF, Bv[1], nullptr, k, nullptr, nullptr, N_ROWS, D_MODEL, D_MODEL);
    tc_gemm<false, false, false><<<gD, 256, TC_SMEM>>>(ahi, alo, whi + WV_OFF, wlo + WV_OFF, Bv[2], nullptr, v, nullptr, nullptr, N_ROWS, D_MODEL, D_MODEL);
    attn_kernel<<<gAtt, 256, ATTN_SMEM>>>(q, k, v, ahi, alo, 1);
    tc_gemm<false, true, false><<<gD, 256, TC_SMEM>>>(ahi, alo, whi + WO_OFF, wlo + WO_OFF, Bv[3], x, x1, nullptr, nullptr, N_ROWS, D_MODEL, D_MODEL);

    // ---- cross-attention block ----
    tsplit_kernel<<<gsq, 256>>>(W[4], whi + CQ_OFF, wlo + CQ_OFF, D_MODEL, D_MODEL);
    tsplit_kernel<<<gsq, 256>>>(W[5], whi + CK_OFF, wlo + CK_OFF, D_MODEL, D_MODEL);
    tsplit_kernel<<<gsq, 256>>>(W[6], whi + CV_OFF, wlo + CV_OFF, D_MODEL, D_MODEL);
    tsplit_kernel<<<gsq, 256>>>(W[7], whi + CO_OFF, wlo + CO_OFF, D_MODEL, D_MODEL);
    split_kernel<<<(N_ROWS * D_MODEL) / 1024, 256>>>(src_x, shi, slo);
    ln_split_kernel<<<N_ROWS, 256>>>(x1, ln2_g, ln2_b, ahi, alo);
    tc_gemm<false, false, false><<<gD, 256, TC_SMEM>>>(ahi, alo, whi + CQ_OFF, wlo + CQ_OFF, Bv[4], nullptr, q, nullptr, nullptr, N_ROWS, D_MODEL, D_MODEL);
    tc_gemm<false, false, false><<<gD, 256, TC_SMEM>>>(shi, slo, whi + CK_OFF, wlo + CK_OFF, Bv[5], nullptr, k, nullptr, nullptr, N_ROWS, D_MODEL, D_MODEL);
    tc_gemm<false, false, false><<<gD, 256, TC_SMEM>>>(shi, slo, whi + CV_OFF, wlo + CV_OFF, Bv[6], nullptr, v, nullptr, nullptr, N_ROWS, D_MODEL, D_MODEL);
    attn_kernel<<<gAtt, 256, ATTN_SMEM>>>(q, k, v, ahi, alo, 0);
    tc_gemm<false, true, false><<<gD, 256, TC_SMEM>>>(ahi, alo, whi + CO_OFF, wlo + CO_OFF, Bv[7], x1, x2, nullptr, nullptr, N_ROWS, D_MODEL, D_MODEL);

    // ---- FFN block ----
    {
        dim3 g1(DFF_ / 32, D_MODEL / 32);
        tsplit_kernel<<<g1, 256>>>(ff_w1, whi + W1_OFF, wlo + W1_OFF, D_MODEL, DFF_);
        dim3 g2(D_MODEL / 32, DFF_ / 32);
        tsplit_kernel<<<g2, 256>>>(ff_w2, whi + W2_OFF, wlo + W2_OFF, DFF_, D_MODEL);
    }
    ln_split_kernel<<<N_ROWS, 256>>>(x2, ln3_g, ln3_b, ahi, alo);
    tc_gemm<true, false, true><<<gF1, 256, TC_SMEM>>>(ahi, alo, whi + W1_OFF, wlo + W1_OFF, ff_b1, nullptr, nullptr, fhi, flo, N_ROWS, DFF_, D_MODEL);
    tc_gemm<false, true, false><<<gD, 256, TC_SMEM>>>(fhi, flo, whi + W2_OFF, wlo + W2_OFF, ff_b2, x2, out, nullptr, nullptr, N_ROWS, D_MODEL, DFF_);
}

// round 9
// speedup vs baseline: 1.5496x; 1.5496x over previous
#include <cuda_runtime.h>
#include <cuda_fp16.h>
#include <math.h>
#include <cstdint>

// ---------------------------------------------------------------------------
// SpectroTFDecoder: pre-LN transformer decoder layer, fp32 I/O.
// GEMMs: mma.sync fp16 tensor cores (single MMA, fp32 accum). Per-operand
// fp16 rounding gives ~2-4e-4 final rel err (threshold 1e-3).
// Attention/LN SIMT fp32; fp16 conversions fused into producers.
// Input order: 0 x, 1 src_x, 2 mask, 3 src_mask, 4-9 ln{1,2,3}_{g,b},
// 10-17 weights (sa_wq,sa_wk,sa_wv,sa_wo,ca_wq,ca_wk,ca_wv,ca_wo),
// 18-25 biases (same order), 26-29 ff_w1,ff_b1,ff_w2,ff_b2.
// ---------------------------------------------------------------------------

#define D_MODEL 1024
#define BATCH   4
#define TSEQ    1024
#define N_ROWS  (BATCH * TSEQ)
#define NHEAD   16
#define DHEAD   64
#define DFF_    4096
#define LN_EPS  1e-6f

// fp32 scratch
__device__ float g_q  [N_ROWS * D_MODEL];
__device__ float g_k  [N_ROWS * D_MODEL];
__device__ float g_v  [N_ROWS * D_MODEL];
__device__ float g_x1 [N_ROWS * D_MODEL];
__device__ float g_x2 [N_ROWS * D_MODEL];

// fp16 scratch
#define WQ_OFF  0
#define WK_OFF  (1 << 20)
#define WV_OFF  (2 << 20)
#define WO_OFF  (3 << 20)
#define CQ_OFF  (4 << 20)
#define CK_OFF  (5 << 20)
#define CV_OFF  (6 << 20)
#define CO_OFF  (7 << 20)
#define W1_OFF  (8 << 20)
#define W2_OFF  (12 << 20)
__device__ __half g_wf16[16 << 20];   // weights (transposed [N,K])
__device__ __half g_af16[4 << 20];    // activation (D-wide)
__device__ __half g_sf16[4 << 20];    // src_x (persistent)
__device__ __half g_ff16[16 << 20];   // FF intermediate

// ---------------------------------------------------------------------------
// asm helpers
// ---------------------------------------------------------------------------
__device__ __forceinline__ uint32_t smem_u32(const void* p) {
    uint32_t a;
    asm("{ .reg .u64 t; cvta.to.shared.u64 t, %1; cvt.u32.u64 %0, t; }"
        : "=r"(a) : "l"(p));
    return a;
}
__device__ __forceinline__ void ldm4(uint32_t* r, uint32_t a) {
    asm volatile("ldmatrix.sync.aligned.m8n8.x4.shared.b16 {%0,%1,%2,%3}, [%4];"
                 : "=r"(r[0]), "=r"(r[1]), "=r"(r[2]), "=r"(r[3]) : "r"(a));
}
__device__ __forceinline__ void mma16816(float* c, const uint32_t* a,
                                         const uint32_t* b) {
    asm volatile(
        "mma.sync.aligned.m16n8k16.row.col.f32.f16.f16.f32 "
        "{%0,%1,%2,%3},{%4,%5,%6,%7},{%8,%9},{%0,%1,%2,%3};"
        : "+f"(c[0]), "+f"(c[1]), "+f"(c[2]), "+f"(c[3])
        : "r"(a[0]), "r"(a[1]), "r"(a[2]), "r"(a[3]), "r"(b[0]), "r"(b[1]));
}

// ---------------------------------------------------------------------------
// f16 convert: fp32 -> fp16. n multiple of 1024.
// ---------------------------------------------------------------------------
__global__ __launch_bounds__(256)
void f16_kernel(const float* __restrict__ in, __half* __restrict__ o)
{
    const int i = (blockIdx.x * 256 + threadIdx.x) * 4;
    float4 a = *(const float4*)(in + i);
    __half2 h01 = __floats2half2_rn(a.x, a.y);
    __half2 h23 = __floats2half2_rn(a.z, a.w);
    *(__half2*)(o + i)     = h01;
    *(__half2*)(o + i + 2) = h23;
}

// ---------------------------------------------------------------------------
// transpose + convert: W[K,N] fp32 -> out[N,K] fp16.
// ---------------------------------------------------------------------------
__global__ __launch_bounds__(256)
void tsplit_kernel(const float* __restrict__ W, __half* __restrict__ o,
                   int K, int N)
{
    __shared__ float t[32][33];
    const int x = threadIdx.x & 31;
    const int y = threadIdx.x >> 5;
    const int k0 = blockIdx.y * 32;
    const int n0 = blockIdx.x * 32;
    #pragma unroll
    for (int r = y; r < 32; r += 8)
        t[r][x] = W[(size_t)(k0 + r) * N + n0 + x];
    __syncthreads();
    #pragma unroll
    for (int r = y; r < 32; r += 8)
        o[(size_t)(n0 + r) * K + k0 + x] = __float2half(t[x][r]);
}

// ---------------------------------------------------------------------------
// LayerNorm fused with fp16 output.
// ---------------------------------------------------------------------------
__global__ __launch_bounds__(256)
void ln_f16_kernel(const float* __restrict__ x, const float* __restrict__ g,
                   const float* __restrict__ bta, __half* __restrict__ o)
{
    const int row = blockIdx.x;
    const int t = threadIdx.x;
    const float* xr = x + (size_t)row * D_MODEL;
    float4 xv = *(const float4*)(xr + t * 4);

    float s = xv.x + xv.y + xv.z + xv.w;
    __shared__ float red[8];
    #pragma unroll
    for (int off = 16; off > 0; off >>= 1) s += __shfl_xor_sync(~0u, s, off);
    if ((t & 31) == 0) red[t >> 5] = s;
    __syncthreads();
    float tot = 0.f;
    #pragma unroll
    for (int i = 0; i < 8; i++) tot += red[i];
    const float mu = tot * (1.f / 1024.f);

    const float dx0 = xv.x - mu, dx1 = xv.y - mu, dx2 = xv.z - mu, dx3 = xv.w - mu;
    float sq = dx0*dx0 + dx1*dx1 + dx2*dx2 + dx3*dx3;
    #pragma unroll
    for (int off = 16; off > 0; off >>= 1) sq += __shfl_xor_sync(~0u, sq, off);
    __syncthreads();
    if ((t & 31) == 0) red[t >> 5] = sq;
    __syncthreads();
    float tot2 = 0.f;
    #pragma unroll
    for (int i = 0; i < 8; i++) tot2 += red[i];
    const float sigma = sqrtf(tot2 * (1.f / 1024.f));
    const float inv = 1.f / (sigma + LN_EPS);

    float4 gv = *(const float4*)(g + t * 4);
    float4 bv = *(const float4*)(bta + t * 4);
    float o0 = dx0 * inv * gv.x + bv.x;
    float o1 = dx1 * inv * gv.y + bv.y;
    float o2 = dx2 * inv * gv.z + bv.z;
    float o3 = dx3 * inv * gv.w + bv.w;

    const size_t off = (size_t)row * D_MODEL + t * 4;
    *(__half2*)(o + off)     = __floats2half2_rn(o0, o1);
    *(__half2*)(o + off + 2) = __floats2half2_rn(o2, o3);
}

// ---------------------------------------------------------------------------
// Tensor-core GEMM, fp16 single-MMA, register-staged double buffer (the
// round-6 skeleton). C[M,N] = A@W + bias (+res), optional ReLU, optional
// fp16 output. A [M,K] fp16 row-major; B = W^T [N,K] fp16 row-major.
// BM=BN=128, BK=32, 8 warps (2x4), warp tile 64x32.
// ---------------------------------------------------------------------------
#define TG_ROW 40                        // padded row stride (fp16 elems)
#define TG_TILE (128 * TG_ROW)           // elems per tile

template<bool RELU, bool RES, bool F16OUT>
__global__ __launch_bounds__(256, 2)
void tc_gemm(const __half* __restrict__ Af, const __half* __restrict__ Bf,
             const float* __restrict__ bias, const float* __restrict__ res,
             float* __restrict__ C, __half* __restrict__ Cf,
             int M, int N, int K)
{
    __shared__ __half As[2][TG_TILE];
    __shared__ __half Bs[2][TG_TILE];
    const uint32_t sbA = smem_u32(&As[0][0]);
    const uint32_t sbB = smem_u32(&Bs[0][0]);
    const int tid = threadIdx.x;
    const int lane = tid & 31;
    const int wid = tid >> 5;
    const int wm = wid >> 2;          // 0..1  (M)
    const int wn = wid & 3;           // 0..3  (N)
    const int bm = blockIdx.y * 128;
    const int bn = blockIdx.x * 128;

    // staging mapping: thread -> (row 0..127, 16-elem half)
    const int srow = tid >> 1;
    const int shalf = (tid & 1) * 16;
    const uint32_t so = (uint32_t)(srow * TG_ROW + shalf) * 2;   // bytes

    const char* gA = (const char*)(Af + (size_t)(bm + srow) * K + shalf);
    const char* gB = (const char*)(Bf + (size_t)(bn + srow) * K + shalf);

    // ldmatrix offsets within a tile
    const uint32_t a_off = (uint32_t)((lane & 15) * TG_ROW * 2 + (lane >> 4) * 16);
    const uint32_t b_off = (uint32_t)((((lane >> 4) << 3) + (lane & 7)) * TG_ROW * 2
                                      + ((lane >> 3) & 1) * 16);
    uint32_t aAddr[4], bAddr[2];
    #pragma unroll
    for (int mt = 0; mt < 4; mt++)
        aAddr[mt] = sbA + (uint32_t)((wm * 64 + mt * 16) * TG_ROW * 2) + a_off;
    #pragma unroll
    for (int ng = 0; ng < 2; ng++)
        bAddr[ng] = sbB + (uint32_t)((wn * 32 + ng * 16) * TG_ROW * 2) + b_off;

    float acc[4][4][4];
    #pragma unroll
    for (int mt = 0; mt < 4; mt++)
        #pragma unroll
        for (int nt = 0; nt < 4; nt++)
            #pragma unroll
            for (int r = 0; r < 4; r++) acc[mt][nt][r] = 0.f;

    // prologue: stage 0
    {
        char* tA = (char*)&As[0][0];
        char* tB = (char*)&Bs[0][0];
        *(uint4*)(tA + so)      = *(const uint4*)gA;
        *(uint4*)(tA + so + 16) = *(const uint4*)(gA + 16);
        *(uint4*)(tB + so)      = *(const uint4*)gB;
        *(uint4*)(tB + so + 16) = *(const uint4*)(gB + 16);
    }
    __syncthreads();

    const int nk = K >> 5;     // BK = 32
    for (int kt = 0; kt < nk; kt++) {
        const int cur = kt & 1;
        const int nxt = cur ^ 1;
        const bool more = (kt + 1 < nk);
        uint4 pa0, pa1, pb0, pb1;
        if (more) {
            const int gb = (kt + 1) * 64;    // 32 elems * 2B
            pa0 = *(const uint4*)(gA + gb);
            pa1 = *(const uint4*)(gA + gb + 16);
            pb0 = *(const uint4*)(gB + gb);
            pb1 = *(const uint4*)(gB + gb + 16);
        }

        const uint32_t stA = (uint32_t)cur * (TG_TILE * 2);
        #pragma unroll
        for (int ks = 0; ks < 2; ks++) {
            const uint32_t kb = stA + ks * 32;
            uint32_t ah[4][4], bh[2][4];
            #pragma unroll
            for (int mt = 0; mt < 4; mt++)
                ldm4(ah[mt], aAddr[mt] + kb);
            #pragma unroll
            for (int ng = 0; ng < 2; ng++)
                ldm4(bh[ng], bAddr[ng] + kb);
            #pragma unroll
            for (int mt = 0; mt < 4; mt++) {
                #pragma unroll
                for (int nt = 0; nt < 4; nt++) {
                    const int ng = nt >> 1;
                    const int hf = (nt & 1) * 2;
                    mma16816(acc[mt][nt], ah[mt], &bh[ng][hf]);
                }
            }
        }

        if (more) {
            char* tA = (char*)&As[nxt][0];
            char* tB = (char*)&Bs[nxt][0];
            *(uint4*)(tA + so)      = pa0;
            *(uint4*)(tA + so + 16) = pa1;
            *(uint4*)(tB + so)      = pb0;
            *(uint4*)(tB + so + 16) = pb1;
        }
        __syncthreads();
    }

    // epilogue
    const int er = lane >> 2;
    const int ec = (lane & 3) * 2;
    #pragma unroll
    for (int mt = 0; mt < 4; mt++) {
        const int row0 = bm + wm * 64 + mt * 16 + er;
        #pragma unroll
        for (int nt = 0; nt < 4; nt++) {
            const int col = bn + wn * 32 + nt * 8 + ec;
            float2 bv = *(const float2*)(bias + col);
            float v0 = acc[mt][nt][0] + bv.x;
            float v1 = acc[mt][nt][1] + bv.y;
            float v2 = acc[mt][nt][2] + bv.x;
            float v3 = acc[mt][nt][3] + bv.y;
            if (RELU) {
                v0 = fmaxf(v0, 0.f); v1 = fmaxf(v1, 0.f);
                v2 = fmaxf(v2, 0.f); v3 = fmaxf(v3, 0.f);
            }
            if (RES) {
                float2 r0 = *(const float2*)(res + (size_t)row0 * N + col);
                float2 r1 = *(const float2*)(res + (size_t)(row0 + 8) * N + col);
                v0 += r0.x; v1 += r0.y; v2 += r1.x; v3 += r1.y;
            }
            if (F16OUT) {
                *(__half2*)(Cf + (size_t)row0 * N + col)       = __floats2half2_rn(v0, v1);
                *(__half2*)(Cf + (size_t)(row0 + 8) * N + col) = __floats2half2_rn(v2, v3);
            } else {
                float2 o0 = {v0, v1};
                float2 o1 = {v2, v3};
                *(float2*)(C + (size_t)row0 * N + col) = o0;
                *(float2*)(C + (size_t)(row0 + 8) * N + col) = o1;
            }
        }
    }
}

// ---------------------------------------------------------------------------
// Flash attention (register-tiled), epilogue writes fp16.
// ---------------------------------------------------------------------------
#define AST 68
#define ATTN_SMEM (4 * 64 * AST * (int)sizeof(float))

__global__ __launch_bounds__(256)
void attn_kernel(const float* __restrict__ Q, const float* __restrict__ Kv,
                 const float* __restrict__ Vv, __half* __restrict__ Of,
                 int causal)
{
    const int qt = blockIdx.x;
    const int h  = blockIdx.y;
    const int b  = blockIdx.z;
    const int tid = threadIdx.x;
    const int ty = tid >> 4;
    const int tx = tid & 15;

    const size_t base = ((size_t)b * TSEQ) * D_MODEL + (size_t)h * DHEAD;

    extern __shared__ __align__(128) char dynsmem[];
    float* sm = (float*)dynsmem;
    float* Qt = sm;
    float* Kt = sm + 64 * AST;
    float* Vs = sm + 2 * 64 * AST;
    float* Pt = sm + 3 * 64 * AST;

    const int r  = tid >> 2;
    const int cc = (tid & 3) * 16;

    {
        const float* src = Q + base + (size_t)(qt * 64 + r) * D_MODEL + cc;
        #pragma unroll
        for (int c = 0; c < 16; c += 4) {
            float4 v4 = *(const float4*)(src + c);
            Qt[(cc + c + 0) * AST + r] = v4.x * 0.125f;
            Qt[(cc + c + 1) * AST + r] = v4.y * 0.125f;
            Qt[(cc + c + 2) * AST + r] = v4.z * 0.125f;
            Qt[(cc + c + 3) * AST + r] = v4.w * 0.125f;
        }
    }

    float m[4], l[4], acc[4][4];
    #pragma unroll
    for (int i = 0; i < 4; i++) {
        m[i] = -INFINITY; l[i] = 0.f;
        #pragma unroll
        for (int j = 0; j < 4; j++) acc[i][j] = 0.f;
    }

    const int ktEnd = causal ? qt : (TSEQ / 64 - 1);

    for (int kt = 0; kt <= ktEnd; kt++) {
        __syncthreads();
        {
            const float* ks = Kv + base + (size_t)(kt * 64 + r) * D_MODEL + cc;
            const float* vs = Vv + base + (size_t)(kt * 64 + r) * D_MODEL + cc;
            #pragma unroll
            for (int c = 0; c < 16; c += 4) {
                float4 k4 = *(const float4*)(ks + c);
                Kt[(cc + c + 0) * AST + r] = k4.x;
                Kt[(cc + c + 1) * AST + r] = k4.y;
                Kt[(cc + c + 2) * AST + r] = k4.z;
                Kt[(cc + c + 3) * AST + r] = k4.w;
                float4 v4 = *(const float4*)(vs + c);
                *(float4*)&Vs[r * AST + cc + c] = v4;
            }
        }
        __syncthreads();

        float s[4][4];
        #pragma unroll
        for (int i = 0; i < 4; i++)
            #pragma unroll
            for (int j = 0; j < 4; j++) s[i][j] = 0.f;
        #pragma unroll 4
        for (int dd = 0; dd < 64; dd++) {
            float4 q4 = *(const float4*)&Qt[dd * AST + 4 * ty];
            float4 k4 = *(const float4*)&Kt[dd * AST + 4 * tx];
            float qa[4] = {q4.x, q4.y, q4.z, q4.w};
            float ka[4] = {k4.x, k4.y, k4.z, k4.w};
            #pragma unroll
            for (int i = 0; i < 4; i++)
                #pragma unroll
                for (int j = 0; j < 4; j++)
                    s[i][j] += qa[i] * ka[j];
        }

        const bool diag = causal && (kt == qt);
        float p[4][4];
        #pragma unroll
        for (int i = 0; i < 4; i++) {
            const int qg = qt * 64 + 4 * ty + i;
            float rmax = -INFINITY;
            #pragma unroll
            for (int j = 0; j < 4; j++) {
                if (diag && (kt * 64 + 4 * tx + j) > qg) s[i][j] = -INFINITY;
                rmax = fmaxf(rmax, s[i][j]);
            }
            rmax = fmaxf(rmax, __shfl_xor_sync(~0u, rmax, 1));
            rmax = fmaxf(rmax, __shfl_xor_sync(~0u, rmax, 2));
            rmax = fmaxf(rmax, __shfl_xor_sync(~0u, rmax, 4));
            rmax = fmaxf(rmax, __shfl_xor_sync(~0u, rmax, 8));
            const float mnew = fmaxf(m[i], rmax);
            const float corr = __expf(m[i] - mnew);
            float rsum = 0.f;
            #pragma unroll
            for (int j = 0; j < 4; j++) {
                p[i][j] = __expf(s[i][j] - mnew);
                rsum += p[i][j];
            }
            rsum += __shfl_xor_sync(~0u, rsum, 1);
            rsum += __shfl_xor_sync(~0u, rsum, 2);
            rsum += __shfl_xor_sync(~0u, rsum, 4);
            rsum += __shfl_xor_sync(~0u, rsum, 8);
            l[i] = l[i] * corr + rsum;
            m[i] = mnew;
            #pragma unroll
            for (int j = 0; j < 4; j++) acc[i][j] *= corr;
        }

        #pragma unroll
        for (int j = 0; j < 4; j++) {
            float4 pj = {p[0][j], p[1][j], p[2][j], p[3][j]};
            *(float4*)&Pt[(4 * tx + j) * AST + 4 * ty] = pj;
        }
        __syncthreads();

        #pragma unroll 4
        for (int kk = 0; kk < 64; kk++) {
            float4 p4 = *(const float4*)&Pt[kk * AST + 4 * ty];
            float4 v4 = *(const float4*)&Vs[kk * AST + 4 * tx];
            float pa[4] = {p4.x, p4.y, p4.z, p4.w};
            float va[4] = {v4.x, v4.y, v4.z, v4.w};
            #pragma unroll
            for (int i = 0; i < 4; i++)
                #pragma unroll
                for (int j = 0; j < 4; j++)
                    acc[i][j] += pa[i] * va[j];
        }
    }

    #pragma unroll
    for (int i = 0; i < 4; i++) {
        const float inv = 1.f / l[i];
        const size_t o = base + (size_t)(qt * 64 + 4 * ty + i) * D_MODEL + 4 * tx;
        *(__half2*)(Of + o)     = __floats2half2_rn(acc[i][0] * inv, acc[i][1] * inv);
        *(__half2*)(Of + o + 2) = __floats2half2_rn(acc[i][2] * inv, acc[i][3] * inv);
    }
}

// ---------------------------------------------------------------------------
// Host orchestration
// ---------------------------------------------------------------------------
extern "C" void kernel_launch(void* const* d_in, const int* in_sizes, int n_in,
                              void* d_out, int out_size)
{
    (void)in_sizes; (void)n_in; (void)out_size;
    const float* x     = (const float*)d_in[0];
    const float* src_x = (const float*)d_in[1];
    const float* ln1_g = (const float*)d_in[4];
    const float* ln1_b = (const float*)d_in[5];
    const float* ln2_g = (const float*)d_in[6];
    const float* ln2_b = (const float*)d_in[7];
    const float* ln3_g = (const float*)d_in[8];
    const float* ln3_b = (const float*)d_in[9];
    const float* W[8];
    for (int i = 0; i < 8; i++) W[i] = (const float*)d_in[10 + i];
    const float* Bv[8];
    for (int i = 0; i < 8; i++) Bv[i] = (const float*)d_in[18 + i];
    const float* ff_w1 = (const float*)d_in[26];
    const float* ff_b1 = (const float*)d_in[27];
    const float* ff_w2 = (const float*)d_in[28];
    const float* ff_b2 = (const float*)d_in[29];
    float* out = (float*)d_out;

    float *q, *k, *v, *x1, *x2;
    cudaGetSymbolAddress((void**)&q,  g_q);
    cudaGetSymbolAddress((void**)&k,  g_k);
    cudaGetSymbolAddress((void**)&v,  g_v);
    cudaGetSymbolAddress((void**)&x1, g_x1);
    cudaGetSymbolAddress((void**)&x2, g_x2);
    __half *wf, *af, *sf, *ff;
    cudaGetSymbolAddress((void**)&wf, g_wf16);
    cudaGetSymbolAddress((void**)&af, g_af16);
    cudaGetSymbolAddress((void**)&sf, g_sf16);
    cudaGetSymbolAddress((void**)&ff, g_ff16);

    cudaFuncSetAttribute(attn_kernel,
                         cudaFuncAttributeMaxDynamicSharedMemorySize, ATTN_SMEM);

    const dim3 gD (D_MODEL / 128, N_ROWS / 128);   // (8, 32)
    const dim3 gF1(DFF_   / 128, N_ROWS / 128);    // (32, 32)
    const dim3 gAtt(TSEQ / 64, NHEAD, BATCH);
    const dim3 gsq(D_MODEL / 32, D_MODEL / 32);

    // ---- launches 0-4: sa weight prep + ln1 ----
    tsplit_kernel<<<gsq, 256>>>(W[0], wf + WQ_OFF, D_MODEL, D_MODEL);
    tsplit_kernel<<<gsq, 256>>>(W[1], wf + WK_OFF, D_MODEL, D_MODEL);
    tsplit_kernel<<<gsq, 256>>>(W[2], wf + WV_OFF, D_MODEL, D_MODEL);
    tsplit_kernel<<<gsq, 256>>>(W[3], wf + WO_OFF, D_MODEL, D_MODEL);
    ln_f16_kernel<<<N_ROWS, 256>>>(x, ln1_g, ln1_b, af);

    // ---- self-attention block ----
    tc_gemm<false, false, false><<<gD, 256>>>(af, wf + WQ_OFF, Bv[0], nullptr, q, nullptr, N_ROWS, D_MODEL, D_MODEL);
    tc_gemm<false, false, false><<<gD, 256>>>(af, wf + WK_OFF, Bv[1], nullptr, k, nullptr, N_ROWS, D_MODEL, D_MODEL);
    tc_gemm<false, false, false><<<gD, 256>>>(af, wf + WV_OFF, Bv[2], nullptr, v, nullptr, N_ROWS, D_MODEL, D_MODEL);
    attn_kernel<<<gAtt, 256, ATTN_SMEM>>>(q, k, v, af, 1);
    tc_gemm<false, true, false><<<gD, 256>>>(af, wf + WO_OFF, Bv[3], x, x1, nullptr, N_ROWS, D_MODEL, D_MODEL);

    // ---- cross-attention block ----
    tsplit_kernel<<<gsq, 256>>>(W[4], wf + CQ_OFF, D_MODEL, D_MODEL);
    tsplit_kernel<<<gsq, 256>>>(W[5], wf + CK_OFF, D_MODEL, D_MODEL);
    tsplit_kernel<<<gsq, 256>>>(W[6], wf + CV_OFF, D_MODEL, D_MODEL);
    tsplit_kernel<<<gsq, 256>>>(W[7], wf + CO_OFF, D_MODEL, D_MODEL);
    f16_kernel<<<(N_ROWS * D_MODEL) / 1024, 256>>>(src_x, sf);
    ln_f16_kernel<<<N_ROWS, 256>>>(x1, ln2_g, ln2_b, af);
    tc_gemm<false, false, false><<<gD, 256>>>(af, wf + CQ_OFF, Bv[4], nullptr, q, nullptr, N_ROWS, D_MODEL, D_MODEL);
    tc_gemm<false, false, false><<<gD, 256>>>(sf, wf + CK_OFF, Bv[5], nullptr, k, nullptr, N_ROWS, D_MODEL, D_MODEL);
    tc_gemm<false, false, false><<<gD, 256>>>(sf, wf + CV_OFF, Bv[6], nullptr, v, nullptr, N_ROWS, D_MODEL, D_MODEL);
    attn_kernel<<<gAtt, 256, ATTN_SMEM>>>(q, k, v, af, 0);
    tc_gemm<false, true, false><<<gD, 256>>>(af, wf + CO_OFF, Bv[7], x1, x2, nullptr, N_ROWS, D_MODEL, D_MODEL);

    // ---- FFN block ----
    {
        dim3 g1(DFF_ / 32, D_MODEL / 32);
        tsplit_kernel<<<g1, 256>>>(ff_w1, wf + W1_OFF, D_MODEL, DFF_);
        dim3 g2(D_MODEL / 32, DFF_ / 32);
        tsplit_kernel<<<g2, 256>>>(ff_w2, wf + W2_OFF, DFF_, D_MODEL);
    }
    ln_f16_kernel<<<N_ROWS, 256>>>(x2, ln3_g, ln3_b, af);
    tc_gemm<true, false, true><<<gF1, 256>>>(af, wf + W1_OFF, ff_b1, nullptr, nullptr, ff, N_ROWS, DFF_, D_MODEL);
    tc_gemm<false, true, false><<<gD, 256>>>(ff, wf + W2_OFF, ff_b2, x2, out, nullptr, N_ROWS, D_MODEL, DFF_);
}

// round 10
// speedup vs baseline: 2.3897x; 1.5421x over previous
#include <cuda_runtime.h>
#include <cuda_fp16.h>
#include <math.h>
#include <cstdint>

// ---------------------------------------------------------------------------
// SpectroTFDecoder: pre-LN transformer decoder layer, fp32 I/O.
// GEMMs + attention on mma.sync fp16 tensor cores (fp32 accum).
// Input order: 0 x, 1 src_x, 2 mask, 3 src_mask, 4-9 ln{1,2,3}_{g,b},
// 10-17 weights (sa_wq,sa_wk,sa_wv,sa_wo,ca_wq,ca_wk,ca_wv,ca_wo),
// 18-25 biases (same order), 26-29 ff_w1,ff_b1,ff_w2,ff_b2.
// ---------------------------------------------------------------------------

#define D_MODEL 1024
#define BATCH   4
#define TSEQ    1024
#define N_ROWS  (BATCH * TSEQ)
#define NHEAD   16
#define DHEAD   64
#define DFF_    4096
#define LN_EPS  1e-6f

// fp32 scratch (residual streams)
__device__ float g_x1 [N_ROWS * D_MODEL];
__device__ float g_x2 [N_ROWS * D_MODEL];

// fp16 scratch
#define WQ_OFF  0
#define WK_OFF  (1 << 20)
#define WV_OFF  (2 << 20)
#define WO_OFF  (3 << 20)
#define CQ_OFF  (4 << 20)
#define CK_OFF  (5 << 20)
#define CV_OFF  (6 << 20)
#define CO_OFF  (7 << 20)
#define W1_OFF  (8 << 20)
#define W2_OFF  (12 << 20)
__device__ __half g_wf16[16 << 20];   // weights (transposed [N,K])
__device__ __half g_af16[4 << 20];    // activation / ctx (D-wide)
__device__ __half g_sf16[4 << 20];    // src_x (persistent)
__device__ __half g_ff16[16 << 20];   // FF intermediate
__device__ __half g_qf16[4 << 20];    // Q
__device__ __half g_kf16[4 << 20];    // K
__device__ __half g_vf16[4 << 20];    // V

// ---------------------------------------------------------------------------
// asm helpers
// ---------------------------------------------------------------------------
__device__ __forceinline__ uint32_t smem_u32(const void* p) {
    uint32_t a;
    asm("{ .reg .u64 t; cvta.to.shared.u64 t, %1; cvt.u32.u64 %0, t; }"
        : "=r"(a) : "l"(p));
    return a;
}
__device__ __forceinline__ void ldm4(uint32_t* r, uint32_t a) {
    asm volatile("ldmatrix.sync.aligned.m8n8.x4.shared.b16 {%0,%1,%2,%3}, [%4];"
                 : "=r"(r[0]), "=r"(r[1]), "=r"(r[2]), "=r"(r[3]) : "r"(a));
}
__device__ __forceinline__ void mma16816(float* c, const uint32_t* a,
                                         const uint32_t* b) {
    asm volatile(
        "mma.sync.aligned.m16n8k16.row.col.f32.f16.f16.f32 "
        "{%0,%1,%2,%3},{%4,%5,%6,%7},{%8,%9},{%0,%1,%2,%3};"
        : "+f"(c[0]), "+f"(c[1]), "+f"(c[2]), "+f"(c[3])
        : "r"(a[0]), "r"(a[1]), "r"(a[2]), "r"(a[3]), "r"(b[0]), "r"(b[1]));
}

// ---------------------------------------------------------------------------
// f16 convert: fp32 -> fp16. n multiple of 1024.
// ---------------------------------------------------------------------------
__global__ __launch_bounds__(256)
void f16_kernel(const float* __restrict__ in, __half* __restrict__ o)
{
    const int i = (blockIdx.x * 256 + threadIdx.x) * 4;
    float4 a = *(const float4*)(in + i);
    *(__half2*)(o + i)     = __floats2half2_rn(a.x, a.y);
    *(__half2*)(o + i + 2) = __floats2half2_rn(a.z, a.w);
}

// ---------------------------------------------------------------------------
// transpose + convert: W[K,N] fp32 -> out[N,K] fp16.
// ---------------------------------------------------------------------------
__global__ __launch_bounds__(256)
void tsplit_kernel(const float* __restrict__ W, __half* __restrict__ o,
                   int K, int N)
{
    __shared__ float t[32][33];
    const int x = threadIdx.x & 31;
    const int y = threadIdx.x >> 5;
    const int k0 = blockIdx.y * 32;
    const int n0 = blockIdx.x * 32;
    #pragma unroll
    for (int r = y; r < 32; r += 8)
        t[r][x] = W[(size_t)(k0 + r) * N + n0 + x];
    __syncthreads();
    #pragma unroll
    for (int r = y; r < 32; r += 8)
        o[(size_t)(n0 + r) * K + k0 + x] = __float2half(t[x][r]);
}

// ---------------------------------------------------------------------------
// LayerNorm fused with fp16 output.
// ---------------------------------------------------------------------------
__global__ __launch_bounds__(256)
void ln_f16_kernel(const float* __restrict__ x, const float* __restrict__ g,
                   const float* __restrict__ bta, __half* __restrict__ o)
{
    const int row = blockIdx.x;
    const int t = threadIdx.x;
    const float* xr = x + (size_t)row * D_MODEL;
    float4 xv = *(const float4*)(xr + t * 4);

    float s = xv.x + xv.y + xv.z + xv.w;
    __shared__ float red[8];
    #pragma unroll
    for (int off = 16; off > 0; off >>= 1) s += __shfl_xor_sync(~0u, s, off);
    if ((t & 31) == 0) red[t >> 5] = s;
    __syncthreads();
    float tot = 0.f;
    #pragma unroll
    for (int i = 0; i < 8; i++) tot += red[i];
    const float mu = tot * (1.f / 1024.f);

    const float dx0 = xv.x - mu, dx1 = xv.y - mu, dx2 = xv.z - mu, dx3 = xv.w - mu;
    float sq = dx0*dx0 + dx1*dx1 + dx2*dx2 + dx3*dx3;
    #pragma unroll
    for (int off = 16; off > 0; off >>= 1) sq += __shfl_xor_sync(~0u, sq, off);
    __syncthreads();
    if ((t & 31) == 0) red[t >> 5] = sq;
    __syncthreads();
    float tot2 = 0.f;
    #pragma unroll
    for (int i = 0; i < 8; i++) tot2 += red[i];
    const float sigma = sqrtf(tot2 * (1.f / 1024.f));
    const float inv = 1.f / (sigma + LN_EPS);

    float4 gv = *(const float4*)(g + t * 4);
    float4 bv = *(const float4*)(bta + t * 4);
    float o0 = dx0 * inv * gv.x + bv.x;
    float o1 = dx1 * inv * gv.y + bv.y;
    float o2 = dx2 * inv * gv.z + bv.z;
    float o3 = dx3 * inv * gv.w + bv.w;

    const size_t off = (size_t)row * D_MODEL + t * 4;
    *(__half2*)(o + off)     = __floats2half2_rn(o0, o1);
    *(__half2*)(o + off + 2) = __floats2half2_rn(o2, o3);
}

// ---------------------------------------------------------------------------
// Tensor-core GEMM, fp16 single-MMA, register-staged double buffer.
// C[M,N] = A@W + bias (+res), optional ReLU, optional fp16 output.
// BM=BN=128, BK=32, 8 warps (2x4), warp tile 64x32.
// ---------------------------------------------------------------------------
#define TG_ROW 40
#define TG_TILE (128 * TG_ROW)

template<bool RELU, bool RES, bool F16OUT>
__global__ __launch_bounds__(256, 2)
void tc_gemm(const __half* __restrict__ Af, const __half* __restrict__ Bf,
             const float* __restrict__ bias, const float* __restrict__ res,
             float* __restrict__ C, __half* __restrict__ Cf,
             int M, int N, int K)
{
    __shared__ __half As[2][TG_TILE];
    __shared__ __half Bs[2][TG_TILE];
    const uint32_t sbA = smem_u32(&As[0][0]);
    const uint32_t sbB = smem_u32(&Bs[0][0]);
    const int tid = threadIdx.x;
    const int lane = tid & 31;
    const int wid = tid >> 5;
    const int wm = wid >> 2;
    const int wn = wid & 3;
    const int bm = blockIdx.y * 128;
    const int bn = blockIdx.x * 128;

    const int srow = tid >> 1;
    const int shalf = (tid & 1) * 16;
    const uint32_t so = (uint32_t)(srow * TG_ROW + shalf) * 2;

    const char* gA = (const char*)(Af + (size_t)(bm + srow) * K + shalf);
    const char* gB = (const char*)(Bf + (size_t)(bn + srow) * K + shalf);

    const uint32_t a_off = (uint32_t)((lane & 15) * TG_ROW * 2 + (lane >> 4) * 16);
    const uint32_t b_off = (uint32_t)((((lane >> 4) << 3) + (lane & 7)) * TG_ROW * 2
                                      + ((lane >> 3) & 1) * 16);
    uint32_t aAddr[4], bAddr[2];
    #pragma unroll
    for (int mt = 0; mt < 4; mt++)
        aAddr[mt] = sbA + (uint32_t)((wm * 64 + mt * 16) * TG_ROW * 2) + a_off;
    #pragma unroll
    for (int ng = 0; ng < 2; ng++)
        bAddr[ng] = sbB + (uint32_t)((wn * 32 + ng * 16) * TG_ROW * 2) + b_off;

    float acc[4][4][4];
    #pragma unroll
    for (int mt = 0; mt < 4; mt++)
        #pragma unroll
        for (int nt = 0; nt < 4; nt++)
            #pragma unroll
            for (int r = 0; r < 4; r++) acc[mt][nt][r] = 0.f;

    {
        char* tA = (char*)&As[0][0];
        char* tB = (char*)&Bs[0][0];
        *(uint4*)(tA + so)      = *(const uint4*)gA;
        *(uint4*)(tA + so + 16) = *(const uint4*)(gA + 16);
        *(uint4*)(tB + so)      = *(const uint4*)gB;
        *(uint4*)(tB + so + 16) = *(const uint4*)(gB + 16);
    }
    __syncthreads();

    const int nk = K >> 5;
    for (int kt = 0; kt < nk; kt++) {
        const int cur = kt & 1;
        const int nxt = cur ^ 1;
        const bool more = (kt + 1 < nk);
        uint4 pa0, pa1, pb0, pb1;
        if (more) {
            const int gb = (kt + 1) * 64;
            pa0 = *(const uint4*)(gA + gb);
            pa1 = *(const uint4*)(gA + gb + 16);
            pb0 = *(const uint4*)(gB + gb);
            pb1 = *(const uint4*)(gB + gb + 16);
        }

        const uint32_t stA = (uint32_t)cur * (TG_TILE * 2);
        #pragma unroll
        for (int ks = 0; ks < 2; ks++) {
            const uint32_t kb = stA + ks * 32;
            uint32_t ah[4][4], bh[2][4];
            #pragma unroll
            for (int mt = 0; mt < 4; mt++)
                ldm4(ah[mt], aAddr[mt] + kb);
            #pragma unroll
            for (int ng = 0; ng < 2; ng++)
                ldm4(bh[ng], bAddr[ng] + kb);
            #pragma unroll
            for (int mt = 0; mt < 4; mt++) {
                #pragma unroll
                for (int nt = 0; nt < 4; nt++) {
                    const int ng = nt >> 1;
                    const int hf = (nt & 1) * 2;
                    mma16816(acc[mt][nt], ah[mt], &bh[ng][hf]);
                }
            }
        }

        if (more) {
            char* tA = (char*)&As[nxt][0];
            char* tB = (char*)&Bs[nxt][0];
            *(uint4*)(tA + so)      = pa0;
            *(uint4*)(tA + so + 16) = pa1;
            *(uint4*)(tB + so)      = pb0;
            *(uint4*)(tB + so + 16) = pb1;
        }
        __syncthreads();
    }

    const int er = lane >> 2;
    const int ec = (lane & 3) * 2;
    #pragma unroll
    for (int mt = 0; mt < 4; mt++) {
        const int row0 = bm + wm * 64 + mt * 16 + er;
        #pragma unroll
        for (int nt = 0; nt < 4; nt++) {
            const int col = bn + wn * 32 + nt * 8 + ec;
            float2 bv = *(const float2*)(bias + col);
            float v0 = acc[mt][nt][0] + bv.x;
            float v1 = acc[mt][nt][1] + bv.y;
            float v2 = acc[mt][nt][2] + bv.x;
            float v3 = acc[mt][nt][3] + bv.y;
            if (RELU) {
                v0 = fmaxf(v0, 0.f); v1 = fmaxf(v1, 0.f);
                v2 = fmaxf(v2, 0.f); v3 = fmaxf(v3, 0.f);
            }
            if (RES) {
                float2 r0 = *(const float2*)(res + (size_t)row0 * N + col);
                float2 r1 = *(const float2*)(res + (size_t)(row0 + 8) * N + col);
                v0 += r0.x; v1 += r0.y; v2 += r1.x; v3 += r1.y;
            }
            if (F16OUT) {
                *(__half2*)(Cf + (size_t)row0 * N + col)       = __floats2half2_rn(v0, v1);
                *(__half2*)(Cf + (size_t)(row0 + 8) * N + col) = __floats2half2_rn(v2, v3);
            } else {
                float2 o0 = {v0, v1};
                float2 o1 = {v2, v3};
                *(float2*)(C + (size_t)row0 * N + col) = o0;
                *(float2*)(C + (size_t)(row0 + 8) * N + col) = o1;
            }
        }
    }
}

// ---------------------------------------------------------------------------
// fp16 tensor-core flash attention (FA2 register scheme).
// Block = 64 q-rows x (head, batch), 128 threads / 4 warps; warp owns 16 rows.
// Q fragments persistent in registers (prescaled by 1/8); K staged natural
// [key][dh]; V staged transposed [dh][key]; P repacked fp16 in registers.
// ---------------------------------------------------------------------------
#define QKST 72   // smem row stride in halves (144 B, 16B-aligned, conflict-free)

__global__ __launch_bounds__(128)
void attn_tc_kernel(const __half* __restrict__ Qf, const __half* __restrict__ Kf,
                    const __half* __restrict__ Vf, __half* __restrict__ Of,
                    int causal)
{
    __shared__ __half Qs[64 * QKST];
    __shared__ __half Ks[64 * QKST];
    __shared__ __half Vt[64 * QKST];
    const int qt = blockIdx.x;
    const int h  = blockIdx.y;
    const int b  = blockIdx.z;
    const int tid = threadIdx.x;
    const int lane = tid & 31;
    const int wid = tid >> 5;
    const size_t base = ((size_t)b * TSEQ) * D_MODEL + (size_t)h * DHEAD;

    // stage Q (scaled by 1/8, exact in fp16)
    {
        const int r = tid >> 1;
        const int hoff = (tid & 1) * 32;
        const __half2 sc = __floats2half2_rn(0.125f, 0.125f);
        const __half2* src = (const __half2*)(Qf + base + (size_t)(qt * 64 + r) * D_MODEL + hoff);
        __half2* dst = (__half2*)(Qs + r * QKST + hoff);
        #pragma unroll
        for (int i = 0; i < 16; i++) dst[i] = __hmul2(src[i], sc);
    }
    __syncthreads();

    const uint32_t a_off = (uint32_t)((lane & 15) * (QKST * 2) + (lane >> 4) * 16);
    const uint32_t b_off = (uint32_t)((((lane >> 4) << 3) + (lane & 7)) * (QKST * 2)
                                      + ((lane >> 3) & 1) * 16);

    // persistent Q fragments: 4 k-steps (dh chunks of 16)
    uint32_t qfr[4][4];
    {
        const uint32_t qa = smem_u32(Qs) + (uint32_t)(wid * 16) * (QKST * 2) + a_off;
        #pragma unroll
        for (int ks = 0; ks < 4; ks++) ldm4(qfr[ks], qa + ks * 32);
    }

    float m0 = -INFINITY, m1 = -INFINITY, l0 = 0.f, l1 = 0.f;
    float ao[8][4];
    #pragma unroll
    for (int nt = 0; nt < 8; nt++)
        #pragma unroll
        for (int r = 0; r < 4; r++) ao[nt][r] = 0.f;

    const uint32_t kbase = smem_u32(Ks);
    const uint32_t vbase = smem_u32(Vt);
    const int gr = lane >> 2;
    const int gc = (lane & 3) * 2;
    const int row0 = qt * 64 + wid * 16 + gr;
    const int row1 = row0 + 8;

    const int ktEnd = causal ? qt : (TSEQ / 64 - 1);
    for (int kt = 0; kt <= ktEnd; kt++) {
        __syncthreads();   // prior reads of Ks/Vt done
        // stage K natural, V transposed
        {
            const int r = tid >> 1;
            const int hoff = (tid & 1) * 32;
            const uint4* ks = (const uint4*)(Kf + base + (size_t)(kt * 64 + r) * D_MODEL + hoff);
            uint4* kd = (uint4*)(Ks + r * QKST + hoff);
            kd[0] = ks[0]; kd[1] = ks[1]; kd[2] = ks[2]; kd[3] = ks[3];
            const __half* vs = Vf + base + (size_t)(kt * 64 + r) * D_MODEL + hoff;
            #pragma unroll
            for (int i = 0; i < 32; i++)
                Vt[(hoff + i) * QKST + r] = vs[i];
        }
        __syncthreads();

        // S = Q @ K^T : 8 key n-tiles of 8
        float s[8][4];
        #pragma unroll
        for (int nt = 0; nt < 8; nt++)
            #pragma unroll
            for (int r = 0; r < 4; r++) s[nt][r] = 0.f;
        #pragma unroll
        for (int g = 0; g < 4; g++) {
            #pragma unroll
            for (int ks = 0; ks < 4; ks++) {
                uint32_t bh[4];
                ldm4(bh, kbase + (uint32_t)(g * 16) * (QKST * 2) + b_off + ks * 32);
                mma16816(s[2 * g],     qfr[ks], &bh[0]);
                mma16816(s[2 * g + 1], qfr[ks], &bh[2]);
            }
        }

        // causal mask + row max
        const bool diag = causal && (kt == qt);
        float rmax0 = -INFINITY, rmax1 = -INFINITY;
        #pragma unroll
        for (int nt = 0; nt < 8; nt++) {
            if (diag) {
                const int c0 = kt * 64 + nt * 8 + gc;
                if (c0 > row0)     s[nt][0] = -INFINITY;
                if (c0 + 1 > row0) s[nt][1] = -INFINITY;
                if (c0 > row1)     s[nt][2] = -INFINITY;
                if (c0 + 1 > row1) s[nt][3] = -INFINITY;
            }
            rmax0 = fmaxf(rmax0, fmaxf(s[nt][0], s[nt][1]));
            rmax1 = fmaxf(rmax1, fmaxf(s[nt][2], s[nt][3]));
        }
        rmax0 = fmaxf(rmax0, __shfl_xor_sync(~0u, rmax0, 1));
        rmax0 = fmaxf(rmax0, __shfl_xor_sync(~0u, rmax0, 2));
        rmax1 = fmaxf(rmax1, __shfl_xor_sync(~0u, rmax1, 1));
        rmax1 = fmaxf(rmax1, __shfl_xor_sync(~0u, rmax1, 2));

        const float mn0 = fmaxf(m0, rmax0);
        const float mn1 = fmaxf(m1, rmax1);
        const float corr0 = __expf(m0 - mn0);
        const float corr1 = __expf(m1 - mn1);
        float rs0 = 0.f, rs1 = 0.f;
        uint32_t pf[8][2];
        #pragma unroll
        for (int nt = 0; nt < 8; nt++) {
            const float p0 = __expf(s[nt][0] - mn0);
            const float p1 = __expf(s[nt][1] - mn0);
            const float p2 = __expf(s[nt][2] - mn1);
            const float p3 = __expf(s[nt][3] - mn1);
            rs0 += p0 + p1;
            rs1 += p2 + p3;
            __half2 h01 = __floats2half2_rn(p0, p1);
            __half2 h23 = __floats2half2_rn(p2, p3);
            pf[nt][0] = *(uint32_t*)&h01;
            pf[nt][1] = *(uint32_t*)&h23;
        }
        rs0 += __shfl_xor_sync(~0u, rs0, 1);
        rs0 += __shfl_xor_sync(~0u, rs0, 2);
        rs1 += __shfl_xor_sync(~0u, rs1, 1);
        rs1 += __shfl_xor_sync(~0u, rs1, 2);
        l0 = l0 * corr0 + rs0;
        l1 = l1 * corr1 + rs1;
        m0 = mn0;
        m1 = mn1;
        #pragma unroll
        for (int nt = 0; nt < 8; nt++) {
            ao[nt][0] *= corr0; ao[nt][1] *= corr0;
            ao[nt][2] *= corr1; ao[nt][3] *= corr1;
        }

        // O += P @ V : 4 key chunks of 16, 4 dh groups of 16
        #pragma unroll
        for (int kc = 0; kc < 4; kc++) {
            uint32_t pa[4] = {pf[2 * kc][0], pf[2 * kc][1],
                              pf[2 * kc + 1][0], pf[2 * kc + 1][1]};
            #pragma unroll
            for (int g = 0; g < 4; g++) {
                uint32_t bv[4];
                ldm4(bv, vbase + (uint32_t)(g * 16) * (QKST * 2) + b_off + kc * 32);
                mma16816(ao[2 * g],     pa, &bv[0]);
                mma16816(ao[2 * g + 1], pa, &bv[2]);
            }
        }
    }

    // epilogue
    const float inv0 = 1.f / l0;
    const float inv1 = 1.f / l1;
    const size_t o0 = base + (size_t)row0 * D_MODEL;
    const size_t o1 = base + (size_t)row1 * D_MODEL;
    #pragma unroll
    for (int nt = 0; nt < 8; nt++) {
        const int col = nt * 8 + gc;
        *(__half2*)(Of + o0 + col) = __floats2half2_rn(ao[nt][0] * inv0, ao[nt][1] * inv0);
        *(__half2*)(Of + o1 + col) = __floats2half2_rn(ao[nt][2] * inv1, ao[nt][3] * inv1);
    }
}

// ---------------------------------------------------------------------------
// Host orchestration
// ---------------------------------------------------------------------------
extern "C" void kernel_launch(void* const* d_in, const int* in_sizes, int n_in,
                              void* d_out, int out_size)
{
    (void)in_sizes; (void)n_in; (void)out_size;
    const float* x     = (const float*)d_in[0];
    const float* src_x = (const float*)d_in[1];
    const float* ln1_g = (const float*)d_in[4];
    const float* ln1_b = (const float*)d_in[5];
    const float* ln2_g = (const float*)d_in[6];
    const float* ln2_b = (const float*)d_in[7];
    const float* ln3_g = (const float*)d_in[8];
    const float* ln3_b = (const float*)d_in[9];
    const float* W[8];
    for (int i = 0; i < 8; i++) W[i] = (const float*)d_in[10 + i];
    const float* Bv[8];
    for (int i = 0; i < 8; i++) Bv[i] = (const float*)d_in[18 + i];
    const float* ff_w1 = (const float*)d_in[26];
    const float* ff_b1 = (const float*)d_in[27];
    const float* ff_w2 = (const float*)d_in[28];
    const float* ff_b2 = (const float*)d_in[29];
    float* out = (float*)d_out;

    float *x1, *x2;
    cudaGetSymbolAddress((void**)&x1, g_x1);
    cudaGetSymbolAddress((void**)&x2, g_x2);
    __half *wf, *af, *sf, *ff, *qf, *kf, *vf;
    cudaGetSymbolAddress((void**)&wf, g_wf16);
    cudaGetSymbolAddress((void**)&af, g_af16);
    cudaGetSymbolAddress((void**)&sf, g_sf16);
    cudaGetSymbolAddress((void**)&ff, g_ff16);
    cudaGetSymbolAddress((void**)&qf, g_qf16);
    cudaGetSymbolAddress((void**)&kf, g_kf16);
    cudaGetSymbolAddress((void**)&vf, g_vf16);

    const dim3 gD (D_MODEL / 128, N_ROWS / 128);   // (8, 32)
    const dim3 gF1(DFF_   / 128, N_ROWS / 128);    // (32, 32)
    const dim3 gAtt(TSEQ / 64, NHEAD, BATCH);
    const dim3 gsq(D_MODEL / 32, D_MODEL / 32);

    // ---- sa weight prep + ln1 ----
    tsplit_kernel<<<gsq, 256>>>(W[0], wf + WQ_OFF, D_MODEL, D_MODEL);
    tsplit_kernel<<<gsq, 256>>>(W[1], wf + WK_OFF, D_MODEL, D_MODEL);
    tsplit_kernel<<<gsq, 256>>>(W[2], wf + WV_OFF, D_MODEL, D_MODEL);
    tsplit_kernel<<<gsq, 256>>>(W[3], wf + WO_OFF, D_MODEL, D_MODEL);
    ln_f16_kernel<<<N_ROWS, 256>>>(x, ln1_g, ln1_b, af);

    // ---- self-attention block ----
    tc_gemm<false, false, true><<<gD, 256>>>(af, wf + WQ_OFF, Bv[0], nullptr, nullptr, qf, N_ROWS, D_MODEL, D_MODEL);
    tc_gemm<false, false, true><<<gD, 256>>>(af, wf + WK_OFF, Bv[1], nullptr, nullptr, kf, N_ROWS, D_MODEL, D_MODEL);
    tc_gemm<false, false, true><<<gD, 256>>>(af, wf + WV_OFF, Bv[2], nullptr, nullptr, vf, N_ROWS, D_MODEL, D_MODEL);
    attn_tc_kernel<<<gAtt, 128>>>(qf, kf, vf, af, 1);
    tc_gemm<false, true, false><<<gD, 256>>>(af, wf + WO_OFF, Bv[3], x, x1, nullptr, N_ROWS, D_MODEL, D_MODEL);

    // ---- cross-attention block ----
    tsplit_kernel<<<gsq, 256>>>(W[4], wf + CQ_OFF, D_MODEL, D_MODEL);
    tsplit_kernel<<<gsq, 256>>>(W[5], wf + CK_OFF, D_MODEL, D_MODEL);
    tsplit_kernel<<<gsq, 256>>>(W[6], wf + CV_OFF, D_MODEL, D_MODEL);
    tsplit_kernel<<<gsq, 256>>>(W[7], wf + CO_OFF, D_MODEL, D_MODEL);
    f16_kernel<<<(N_ROWS * D_MODEL) / 1024, 256>>>(src_x, sf);
    ln_f16_kernel<<<N_ROWS, 256>>>(x1, ln2_g, ln2_b, af);
    tc_gemm<false, false, true><<<gD, 256>>>(af, wf + CQ_OFF, Bv[4], nullptr, nullptr, qf, N_ROWS, D_MODEL, D_MODEL);
    tc_gemm<false, false, true><<<gD, 256>>>(sf, wf + CK_OFF, Bv[5], nullptr, nullptr, kf, N_ROWS, D_MODEL, D_MODEL);
    tc_gemm<false, false, true><<<gD, 256>>>(sf, wf + CV_OFF, Bv[6], nullptr, nullptr, vf, N_ROWS, D_MODEL, D_MODEL);
    attn_tc_kernel<<<gAtt, 128>>>(qf, kf, vf, af, 0);
    tc_gemm<false, true, false><<<gD, 256>>>(af, wf + CO_OFF, Bv[7], x1, x2, nullptr, N_ROWS, D_MODEL, D_MODEL);

    // ---- FFN block ----
    {
        dim3 g1(DFF_ / 32, D_MODEL / 32);
        tsplit_kernel<<<g1, 256>>>(ff_w1, wf + W1_OFF, D_MODEL, DFF_);
        dim3 g2(D_MODEL / 32, DFF_ / 32);
        tsplit_kernel<<<g2, 256>>>(ff_w2, wf + W2_OFF, DFF_, D_MODEL);
    }
    ln_f16_kernel<<<N_ROWS, 256>>>(x2, ln3_g, ln3_b, af);
    tc_gemm<true, false, true><<<gF1, 256>>>(af, wf + W1_OFF, ff_b1, nullptr, nullptr, ff, N_ROWS, DFF_, D_MODEL);
    tc_gemm<false, true, false><<<gD, 256>>>(ff, wf + W2_OFF, ff_b2, x2, out, nullptr, N_ROWS, D_MODEL, DFF_);
}

// round 11
// speedup vs baseline: 2.8644x; 1.1987x over previous
#include <cuda_runtime.h>
#include <cuda_fp16.h>
#include <math.h>
#include <cstdint>

// ---------------------------------------------------------------------------
// SpectroTFDecoder: pre-LN transformer decoder layer, fp32 I/O.
// GEMMs + attention on mma.sync fp16 tensor cores (fp32 accum).
// QKV projections fused into one N=3072 GEMM; cross K/V fused N=2048.
// Attention: FA2 register scheme, V consumed via ldmatrix.trans (no scalar
// transpose staging).
// Input order: 0 x, 1 src_x, 2 mask, 3 src_mask, 4-9 ln{1,2,3}_{g,b},
// 10-17 weights (sa_wq,sa_wk,sa_wv,sa_wo,ca_wq,ca_wk,ca_wv,ca_wo),
// 18-25 biases (same order), 26-29 ff_w1,ff_b1,ff_w2,ff_b2.
// ---------------------------------------------------------------------------

#define D_MODEL 1024
#define BATCH   4
#define TSEQ    1024
#define N_ROWS  (BATCH * TSEQ)
#define NHEAD   16
#define DHEAD   64
#define DFF_    4096
#define LN_EPS  1e-6f

// fp32 scratch (residual streams + fused biases)
__device__ float g_x1 [N_ROWS * D_MODEL];
__device__ float g_x2 [N_ROWS * D_MODEL];
__device__ float g_bqkv[3 * D_MODEL];
__device__ float g_bkv [2 * D_MODEL];

// fp16 scratch
#define WQ_OFF  0
#define WK_OFF  (1 << 20)
#define WV_OFF  (2 << 20)
#define WO_OFF  (3 << 20)
#define CQ_OFF  (4 << 20)
#define CK_OFF  (5 << 20)
#define CV_OFF  (6 << 20)
#define CO_OFF  (7 << 20)
#define W1_OFF  (8 << 20)
#define W2_OFF  (12 << 20)
__device__ __half g_wf16[16 << 20];   // weights (transposed [N,K])
__device__ __half g_af16[4 << 20];    // activation / ctx (D-wide)
__device__ __half g_sf16[4 << 20];    // src_x (persistent)
__device__ __half g_ff16[16 << 20];   // FF intermediate / ca-Q scratch
__device__ __half g_qkv [12 << 20];   // fused QKV [4096,3072] / ca-KV [4096,2048]

// ---------------------------------------------------------------------------
// asm helpers
// ---------------------------------------------------------------------------
__device__ __forceinline__ uint32_t smem_u32(const void* p) {
    uint32_t a;
    asm("{ .reg .u64 t; cvta.to.shared.u64 t, %1; cvt.u32.u64 %0, t; }"
        : "=r"(a) : "l"(p));
    return a;
}
__device__ __forceinline__ void ldm4(uint32_t* r, uint32_t a) {
    asm volatile("ldmatrix.sync.aligned.m8n8.x4.shared.b16 {%0,%1,%2,%3}, [%4];"
                 : "=r"(r[0]), "=r"(r[1]), "=r"(r[2]), "=r"(r[3]) : "r"(a));
}
__device__ __forceinline__ void ldm4t(uint32_t* r, uint32_t a) {
    asm volatile("ldmatrix.sync.aligned.m8n8.x4.trans.shared.b16 {%0,%1,%2,%3}, [%4];"
                 : "=r"(r[0]), "=r"(r[1]), "=r"(r[2]), "=r"(r[3]) : "r"(a));
}
__device__ __forceinline__ void mma16816(float* c, const uint32_t* a,
                                         const uint32_t* b) {
    asm volatile(
        "mma.sync.aligned.m16n8k16.row.col.f32.f16.f16.f32 "
        "{%0,%1,%2,%3},{%4,%5,%6,%7},{%8,%9},{%0,%1,%2,%3};"
        : "+f"(c[0]), "+f"(c[1]), "+f"(c[2]), "+f"(c[3])
        : "r"(a[0]), "r"(a[1]), "r"(a[2]), "r"(a[3]), "r"(b[0]), "r"(b[1]));
}

// ---------------------------------------------------------------------------
// f16 convert: fp32 -> fp16. n multiple of 1024.
// ---------------------------------------------------------------------------
__global__ __launch_bounds__(256)
void f16_kernel(const float* __restrict__ in, __half* __restrict__ o)
{
    const int i = (blockIdx.x * 256 + threadIdx.x) * 4;
    float4 a = *(const float4*)(in + i);
    *(__half2*)(o + i)     = __floats2half2_rn(a.x, a.y);
    *(__half2*)(o + i + 2) = __floats2half2_rn(a.z, a.w);
}

// ---------------------------------------------------------------------------
// bias concat: o[0:1024)=b0, [1024:2048)=b1, [2048:3072)=b2 (grid sized by n).
// ---------------------------------------------------------------------------
__global__ __launch_bounds__(256)
void catbias_kernel(const float* __restrict__ b0, const float* __restrict__ b1,
                    const float* __restrict__ b2, float* __restrict__ o)
{
    const int i = blockIdx.x * 256 + threadIdx.x;
    const float* s = (i < 1024) ? b0 : ((i < 2048) ? b1 : b2);
    o[i] = s[i & 1023];
}

// ---------------------------------------------------------------------------
// batched transpose+convert for the 8 square weights: W[1024,1024] -> [N,K] f16
// ---------------------------------------------------------------------------
struct WPtrs { const float* p[8]; };

__global__ __launch_bounds__(256)
void tsplit8_kernel(WPtrs ws, __half* __restrict__ obase)
{
    __shared__ float t[32][33];
    const float* W = ws.p[blockIdx.z];
    __half* o = obase + ((size_t)blockIdx.z << 20);
    const int x = threadIdx.x & 31;
    const int y = threadIdx.x >> 5;
    const int k0 = blockIdx.y * 32;
    const int n0 = blockIdx.x * 32;
    #pragma unroll
    for (int r = y; r < 32; r += 8)
        t[r][x] = W[(size_t)(k0 + r) * D_MODEL + n0 + x];
    __syncthreads();
    #pragma unroll
    for (int r = y; r < 32; r += 8)
        o[(size_t)(n0 + r) * D_MODEL + k0 + x] = __float2half(t[x][r]);
}

// single-weight version (FFN weights, rectangular)
__global__ __launch_bounds__(256)
void tsplit_kernel(const float* __restrict__ W, __half* __restrict__ o,
                   int K, int N)
{
    __shared__ float t[32][33];
    const int x = threadIdx.x & 31;
    const int y = threadIdx.x >> 5;
    const int k0 = blockIdx.y * 32;
    const int n0 = blockIdx.x * 32;
    #pragma unroll
    for (int r = y; r < 32; r += 8)
        t[r][x] = W[(size_t)(k0 + r) * N + n0 + x];
    __syncthreads();
    #pragma unroll
    for (int r = y; r < 32; r += 8)
        o[(size_t)(n0 + r) * K + k0 + x] = __float2half(t[x][r]);
}

// ---------------------------------------------------------------------------
// LayerNorm fused with fp16 output.
// ---------------------------------------------------------------------------
__global__ __launch_bounds__(256)
void ln_f16_kernel(const float* __restrict__ x, const float* __restrict__ g,
                   const float* __restrict__ bta, __half* __restrict__ o)
{
    const int row = blockIdx.x;
    const int t = threadIdx.x;
    const float* xr = x + (size_t)row * D_MODEL;
    float4 xv = *(const float4*)(xr + t * 4);

    float s = xv.x + xv.y + xv.z + xv.w;
    __shared__ float red[8];
    #pragma unroll
    for (int off = 16; off > 0; off >>= 1) s += __shfl_xor_sync(~0u, s, off);
    if ((t & 31) == 0) red[t >> 5] = s;
    __syncthreads();
    float tot = 0.f;
    #pragma unroll
    for (int i = 0; i < 8; i++) tot += red[i];
    const float mu = tot * (1.f / 1024.f);

    const float dx0 = xv.x - mu, dx1 = xv.y - mu, dx2 = xv.z - mu, dx3 = xv.w - mu;
    float sq = dx0*dx0 + dx1*dx1 + dx2*dx2 + dx3*dx3;
    #pragma unroll
    for (int off = 16; off > 0; off >>= 1) sq += __shfl_xor_sync(~0u, sq, off);
    __syncthreads();
    if ((t & 31) == 0) red[t >> 5] = sq;
    __syncthreads();
    float tot2 = 0.f;
    #pragma unroll
    for (int i = 0; i < 8; i++) tot2 += red[i];
    const float sigma = sqrtf(tot2 * (1.f / 1024.f));
    const float inv = 1.f / (sigma + LN_EPS);

    float4 gv = *(const float4*)(g + t * 4);
    float4 bv = *(const float4*)(bta + t * 4);
    float o0 = dx0 * inv * gv.x + bv.x;
    float o1 = dx1 * inv * gv.y + bv.y;
    float o2 = dx2 * inv * gv.z + bv.z;
    float o3 = dx3 * inv * gv.w + bv.w;

    const size_t off = (size_t)row * D_MODEL + t * 4;
    *(__half2*)(o + off)     = __floats2half2_rn(o0, o1);
    *(__half2*)(o + off + 2) = __floats2half2_rn(o2, o3);
}

// ---------------------------------------------------------------------------
// Tensor-core GEMM, fp16 single-MMA, register-staged double buffer.
// C[M,N] = A@W + bias (+res), optional ReLU, optional fp16 output.
// BM=BN=128, BK=32, 8 warps (2x4), warp tile 64x32.
// ---------------------------------------------------------------------------
#define TG_ROW 40
#define TG_TILE (128 * TG_ROW)

template<bool RELU, bool RES, bool F16OUT>
__global__ __launch_bounds__(256, 2)
void tc_gemm(const __half* __restrict__ Af, const __half* __restrict__ Bf,
             const float* __restrict__ bias, const float* __restrict__ res,
             float* __restrict__ C, __half* __restrict__ Cf,
             int M, int N, int K)
{
    __shared__ __half As[2][TG_TILE];
    __shared__ __half Bs[2][TG_TILE];
    const uint32_t sbA = smem_u32(&As[0][0]);
    const uint32_t sbB = smem_u32(&Bs[0][0]);
    const int tid = threadIdx.x;
    const int lane = tid & 31;
    const int wid = tid >> 5;
    const int wm = wid >> 2;
    const int wn = wid & 3;
    const int bm = blockIdx.y * 128;
    const int bn = blockIdx.x * 128;

    const int srow = tid >> 1;
    const int shalf = (tid & 1) * 16;
    const uint32_t so = (uint32_t)(srow * TG_ROW + shalf) * 2;

    const char* gA = (const char*)(Af + (size_t)(bm + srow) * K + shalf);
    const char* gB = (const char*)(Bf + (size_t)(bn + srow) * K + shalf);

    const uint32_t a_off = (uint32_t)((lane & 15) * TG_ROW * 2 + (lane >> 4) * 16);
    const uint32_t b_off = (uint32_t)((((lane >> 4) << 3) + (lane & 7)) * TG_ROW * 2
                                      + ((lane >> 3) & 1) * 16);
    uint32_t aAddr[4], bAddr[2];
    #pragma unroll
    for (int mt = 0; mt < 4; mt++)
        aAddr[mt] = sbA + (uint32_t)((wm * 64 + mt * 16) * TG_ROW * 2) + a_off;
    #pragma unroll
    for (int ng = 0; ng < 2; ng++)
        bAddr[ng] = sbB + (uint32_t)((wn * 32 + ng * 16) * TG_ROW * 2) + b_off;

    float acc[4][4][4];
    #pragma unroll
    for (int mt = 0; mt < 4; mt++)
        #pragma unroll
        for (int nt = 0; nt < 4; nt++)
            #pragma unroll
            for (int r = 0; r < 4; r++) acc[mt][nt][r] = 0.f;

    {
        char* tA = (char*)&As[0][0];
        char* tB = (char*)&Bs[0][0];
        *(uint4*)(tA + so)      = *(const uint4*)gA;
        *(uint4*)(tA + so + 16) = *(const uint4*)(gA + 16);
        *(uint4*)(tB + so)      = *(const uint4*)gB;
        *(uint4*)(tB + so + 16) = *(const uint4*)(gB + 16);
    }
    __syncthreads();

    const int nk = K >> 5;
    for (int kt = 0; kt < nk; kt++) {
        const int cur = kt & 1;
        const int nxt = cur ^ 1;
        const bool more = (kt + 1 < nk);
        uint4 pa0, pa1, pb0, pb1;
        if (more) {
            const int gb = (kt + 1) * 64;
            pa0 = *(const uint4*)(gA + gb);
            pa1 = *(const uint4*)(gA + gb + 16);
            pb0 = *(const uint4*)(gB + gb);
            pb1 = *(const uint4*)(gB + gb + 16);
        }

        const uint32_t stA = (uint32_t)cur * (TG_TILE * 2);
        #pragma unroll
        for (int ks = 0; ks < 2; ks++) {
            const uint32_t kb = stA + ks * 32;
            uint32_t ah[4][4], bh[2][4];
            #pragma unroll
            for (int mt = 0; mt < 4; mt++)
                ldm4(ah[mt], aAddr[mt] + kb);
            #pragma unroll
            for (int ng = 0; ng < 2; ng++)
                ldm4(bh[ng], bAddr[ng] + kb);
            #pragma unroll
            for (int mt = 0; mt < 4; mt++) {
                #pragma unroll
                for (int nt = 0; nt < 4; nt++) {
                    const int ng = nt >> 1;
                    const int hf = (nt & 1) * 2;
                    mma16816(acc[mt][nt], ah[mt], &bh[ng][hf]);
                }
            }
        }

        if (more) {
            char* tA = (char*)&As[nxt][0];
            char* tB = (char*)&Bs[nxt][0];
            *(uint4*)(tA + so)      = pa0;
            *(uint4*)(tA + so + 16) = pa1;
            *(uint4*)(tB + so)      = pb0;
            *(uint4*)(tB + so + 16) = pb1;
        }
        __syncthreads();
    }

    const int er = lane >> 2;
    const int ec = (lane & 3) * 2;
    #pragma unroll
    for (int mt = 0; mt < 4; mt++) {
        const int row0 = bm + wm * 64 + mt * 16 + er;
        #pragma unroll
        for (int nt = 0; nt < 4; nt++) {
            const int col = bn + wn * 32 + nt * 8 + ec;
            float2 bv = *(const float2*)(bias + col);
            float v0 = acc[mt][nt][0] + bv.x;
            float v1 = acc[mt][nt][1] + bv.y;
            float v2 = acc[mt][nt][2] + bv.x;
            float v3 = acc[mt][nt][3] + bv.y;
            if (RELU) {
                v0 = fmaxf(v0, 0.f); v1 = fmaxf(v1, 0.f);
                v2 = fmaxf(v2, 0.f); v3 = fmaxf(v3, 0.f);
            }
            if (RES) {
                float2 r0 = *(const float2*)(res + (size_t)row0 * N + col);
                float2 r1 = *(const float2*)(res + (size_t)(row0 + 8) * N + col);
                v0 += r0.x; v1 += r0.y; v2 += r1.x; v3 += r1.y;
            }
            if (F16OUT) {
                *(__half2*)(Cf + (size_t)row0 * N + col)       = __floats2half2_rn(v0, v1);
                *(__half2*)(Cf + (size_t)(row0 + 8) * N + col) = __floats2half2_rn(v2, v3);
            } else {
                float2 o0 = {v0, v1};
                float2 o1 = {v2, v3};
                *(float2*)(C + (size_t)row0 * N + col) = o0;
                *(float2*)(C + (size_t)(row0 + 8) * N + col) = o1;
            }
        }
    }
}

// ---------------------------------------------------------------------------
// fp16 tensor-core flash attention (FA2 register scheme).
// Block = 64 q-rows x (head, batch), 128 threads / 4 warps; warp owns 16 rows.
// Q fragments persistent in registers (prescaled by 1/8); K and V both staged
// NATURAL [key][dh] with vectorized copies; V consumed via ldmatrix.trans.
// Strided Q/K/V pointers support fused-QKV layouts. Output stride = D_MODEL.
// ---------------------------------------------------------------------------
#define QKST 72   // smem row stride in halves (144 B, conflict-free)

__global__ __launch_bounds__(128)
void attn_tc_kernel(const __half* __restrict__ Qf, const __half* __restrict__ Kf,
                    const __half* __restrict__ Vf, __half* __restrict__ Of,
                    int ldq, int ldkv, int causal)
{
    __shared__ __half Qs[64 * QKST];
    __shared__ __half Ks[64 * QKST];
    __shared__ __half Vs[64 * QKST];
    const int qt = blockIdx.x;
    const int h  = blockIdx.y;
    const int b  = blockIdx.z;
    const int tid = threadIdx.x;
    const int lane = tid & 31;
    const int wid = tid >> 5;
    const size_t qrow0 = (size_t)b * TSEQ;

    // stage Q (scaled by 1/8, exact in fp16)
    {
        const int r = tid >> 1;
        const int hoff = (tid & 1) * 32;
        const __half2 sc = __floats2half2_rn(0.125f, 0.125f);
        const __half2* src = (const __half2*)(Qf + (qrow0 + qt * 64 + r) * ldq
                                              + h * DHEAD + hoff);
        __half2* dst = (__half2*)(Qs + r * QKST + hoff);
        #pragma unroll
        for (int i = 0; i < 16; i++) dst[i] = __hmul2(src[i], sc);
    }
    __syncthreads();

    const uint32_t a_off = (uint32_t)((lane & 15) * (QKST * 2) + (lane >> 4) * 16);
    const uint32_t b_off = (uint32_t)((((lane >> 4) << 3) + (lane & 7)) * (QKST * 2)
                                      + ((lane >> 3) & 1) * 16);

    // persistent Q fragments: 4 k-steps (dh chunks of 16)
    uint32_t qfr[4][4];
    {
        const uint32_t qa = smem_u32(Qs) + (uint32_t)(wid * 16) * (QKST * 2) + a_off;
        #pragma unroll
        for (int ks = 0; ks < 4; ks++) ldm4(qfr[ks], qa + ks * 32);
    }

    float m0 = -INFINITY, m1 = -INFINITY, l0 = 0.f, l1 = 0.f;
    float ao[8][4];
    #pragma unroll
    for (int nt = 0; nt < 8; nt++)
        #pragma unroll
        for (int r = 0; r < 4; r++) ao[nt][r] = 0.f;

    const uint32_t kbase = smem_u32(Ks);
    const uint32_t vbase = smem_u32(Vs);
    const int gr = lane >> 2;
    const int gc = (lane & 3) * 2;
    const int row0 = qt * 64 + wid * 16 + gr;
    const int row1 = row0 + 8;

    const int ktEnd = causal ? qt : (TSEQ / 64 - 1);
    for (int kt = 0; kt <= ktEnd; kt++) {
        __syncthreads();   // prior reads of Ks/Vs done
        // stage K and V natural (vectorized)
        {
            const int r = tid >> 1;
            const int hoff = (tid & 1) * 32;
            const size_t goff = (qrow0 + kt * 64 + r) * (size_t)ldkv + h * DHEAD + hoff;
            const uint4* ks = (const uint4*)(Kf + goff);
            const uint4* vs = (const uint4*)(Vf + goff);
            uint4* kd = (uint4*)(Ks + r * QKST + hoff);
            uint4* vd = (uint4*)(Vs + r * QKST + hoff);
            kd[0] = ks[0]; kd[1] = ks[1]; kd[2] = ks[2]; kd[3] = ks[3];
            vd[0] = vs[0]; vd[1] = vs[1]; vd[2] = vs[2]; vd[3] = vs[3];
        }
        __syncthreads();

        // S = Q @ K^T : 8 key n-tiles of 8
        float s[8][4];
        #pragma unroll
        for (int nt = 0; nt < 8; nt++)
            #pragma unroll
            for (int r = 0; r < 4; r++) s[nt][r] = 0.f;
        #pragma unroll
        for (int g = 0; g < 4; g++) {
            #pragma unroll
            for (int ks = 0; ks < 4; ks++) {
                uint32_t bh[4];
                ldm4(bh, kbase + (uint32_t)(g * 16) * (QKST * 2) + b_off + ks * 32);
                mma16816(s[2 * g],     qfr[ks], &bh[0]);
                mma16816(s[2 * g + 1], qfr[ks], &bh[2]);
            }
        }

        // causal mask + row max
        const bool diag = causal && (kt == qt);
        float rmax0 = -INFINITY, rmax1 = -INFINITY;
        #pragma unroll
        for (int nt = 0; nt < 8; nt++) {
            if (diag) {
                const int c0 = kt * 64 + nt * 8 + gc;
                if (c0 > row0)     s[nt][0] = -INFINITY;
                if (c0 + 1 > row0) s[nt][1] = -INFINITY;
                if (c0 > row1)     s[nt][2] = -INFINITY;
                if (c0 + 1 > row1) s[nt][3] = -INFINITY;
            }
            rmax0 = fmaxf(rmax0, fmaxf(s[nt][0], s[nt][1]));
            rmax1 = fmaxf(rmax1, fmaxf(s[nt][2], s[nt][3]));
        }
        rmax0 = fmaxf(rmax0, __shfl_xor_sync(~0u, rmax0, 1));
        rmax0 = fmaxf(rmax0, __shfl_xor_sync(~0u, rmax0, 2));
        rmax1 = fmaxf(rmax1, __shfl_xor_sync(~0u, rmax1, 1));
        rmax1 = fmaxf(rmax1, __shfl_xor_sync(~0u, rmax1, 2));

        const float mn0 = fmaxf(m0, rmax0);
        const float mn1 = fmaxf(m1, rmax1);
        const float corr0 = __expf(m0 - mn0);
        const float corr1 = __expf(m1 - mn1);
        float rs0 = 0.f, rs1 = 0.f;
        uint32_t pf[8][2];
        #pragma unroll
        for (int nt = 0; nt < 8; nt++) {
            const float p0 = __expf(s[nt][0] - mn0);
            const float p1 = __expf(s[nt][1] - mn0);
            const float p2 = __expf(s[nt][2] - mn1);
            const float p3 = __expf(s[nt][3] - mn1);
            rs0 += p0 + p1;
            rs1 += p2 + p3;
            __half2 h01 = __floats2half2_rn(p0, p1);
            __half2 h23 = __floats2half2_rn(p2, p3);
            pf[nt][0] = *(uint32_t*)&h01;
            pf[nt][1] = *(uint32_t*)&h23;
        }
        rs0 += __shfl_xor_sync(~0u, rs0, 1);
        rs0 += __shfl_xor_sync(~0u, rs0, 2);
        rs1 += __shfl_xor_sync(~0u, rs1, 1);
        rs1 += __shfl_xor_sync(~0u, rs1, 2);
        l0 = l0 * corr0 + rs0;
        l1 = l1 * corr1 + rs1;
        m0 = mn0;
        m1 = mn1;
        #pragma unroll
        for (int nt = 0; nt < 8; nt++) {
            ao[nt][0] *= corr0; ao[nt][1] *= corr0;
            ao[nt][2] *= corr1; ao[nt][3] *= corr1;
        }

        // O += P @ V : V^T fragments via ldmatrix.trans on natural V
        #pragma unroll
        for (int kc = 0; kc < 4; kc++) {
            uint32_t pa[4] = {pf[2 * kc][0], pf[2 * kc][1],
                              pf[2 * kc + 1][0], pf[2 * kc + 1][1]};
            const uint32_t vrow = vbase + (uint32_t)(kc * 16) * (QKST * 2) + a_off;
            #pragma unroll
            for (int g = 0; g < 4; g++) {
                uint32_t bv[4];
                ldm4t(bv, vrow + g * 32);
                mma16816(ao[2 * g],     pa, &bv[0]);
                mma16816(ao[2 * g + 1], pa, &bv[2]);
            }
        }
    }

    // epilogue (output stride = D_MODEL)
    const float inv0 = 1.f / l0;
    const float inv1 = 1.f / l1;
    const size_t o0 = (qrow0 + row0) * D_MODEL + h * DHEAD;
    const size_t o1 = (qrow0 + row1) * D_MODEL + h * DHEAD;
    #pragma unroll
    for (int nt = 0; nt < 8; nt++) {
        const int col = nt * 8 + gc;
        *(__half2*)(Of + o0 + col) = __floats2half2_rn(ao[nt][0] * inv0, ao[nt][1] * inv0);
        *(__half2*)(Of + o1 + col) = __floats2half2_rn(ao[nt][2] * inv1, ao[nt][3] * inv1);
    }
}

// ---------------------------------------------------------------------------
// Host orchestration
// ---------------------------------------------------------------------------
extern "C" void kernel_launch(void* const* d_in, const int* in_sizes, int n_in,
                              void* d_out, int out_size)
{
    (void)in_sizes; (void)n_in; (void)out_size;
    const float* x     = (const float*)d_in[0];
    const float* src_x = (const float*)d_in[1];
    const float* ln1_g = (const float*)d_in[4];
    const float* ln1_b = (const float*)d_in[5];
    const float* ln2_g = (const float*)d_in[6];
    const float* ln2_b = (const float*)d_in[7];
    const float* ln3_g = (const float*)d_in[8];
    const float* ln3_b = (const float*)d_in[9];
    const float* W[8];
    for (int i = 0; i < 8; i++) W[i] = (const float*)d_in[10 + i];
    const float* Bv[8];
    for (int i = 0; i < 8; i++) Bv[i] = (const float*)d_in[18 + i];
    const float* ff_w1 = (const float*)d_in[26];
    const float* ff_b1 = (const float*)d_in[27];
    const float* ff_w2 = (const float*)d_in[28];
    const float* ff_b2 = (const float*)d_in[29];
    float* out = (float*)d_out;

    float *x1, *x2, *bqkv, *bkv;
    cudaGetSymbolAddress((void**)&x1, g_x1);
    cudaGetSymbolAddress((void**)&x2, g_x2);
    cudaGetSymbolAddress((void**)&bqkv, g_bqkv);
    cudaGetSymbolAddress((void**)&bkv,  g_bkv);
    __half *wf, *af, *sf, *ff, *qkv;
    cudaGetSymbolAddress((void**)&wf,  g_wf16);
    cudaGetSymbolAddress((void**)&af,  g_af16);
    cudaGetSymbolAddress((void**)&sf,  g_sf16);
    cudaGetSymbolAddress((void**)&ff,  g_ff16);
    cudaGetSymbolAddress((void**)&qkv, g_qkv);

    const dim3 gQKV(3 * D_MODEL / 128, N_ROWS / 128);   // (24, 32)
    const dim3 gKV (2 * D_MODEL / 128, N_ROWS / 128);   // (16, 32)
    const dim3 gD  (D_MODEL / 128, N_ROWS / 128);       // (8, 32)
    const dim3 gF1 (DFF_   / 128, N_ROWS / 128);        // (32, 32)
    const dim3 gAtt(TSEQ / 64, NHEAD, BATCH);

    // ---- weight prep (batched) + biases + ln1 ----
    {
        WPtrs ws;
        for (int i = 0; i < 8; i++) ws.p[i] = W[i];
        dim3 g8(D_MODEL / 32, D_MODEL / 32, 8);
        tsplit8_kernel<<<g8, 256>>>(ws, wf);
        dim3 g1(DFF_ / 32, D_MODEL / 32);
        tsplit_kernel<<<g1, 256>>>(ff_w1, wf + W1_OFF, D_MODEL, DFF_);
        dim3 g2(D_MODEL / 32, DFF_ / 32);
        tsplit_kernel<<<g2, 256>>>(ff_w2, wf + W2_OFF, DFF_, D_MODEL);
    }
    catbias_kernel<<<12, 256>>>(Bv[0], Bv[1], Bv[2], bqkv);
    catbias_kernel<<<8, 256>>>(Bv[5], Bv[6], Bv[6], bkv);
    f16_kernel<<<(N_ROWS * D_MODEL) / 1024, 256>>>(src_x, sf);
    ln_f16_kernel<<<N_ROWS, 256>>>(x, ln1_g, ln1_b, af);

    // ---- self-attention block (fused QKV) ----
    tc_gemm<false, false, true><<<gQKV, 256>>>(af, wf + WQ_OFF, bqkv, nullptr, nullptr, qkv, N_ROWS, 3 * D_MODEL, D_MODEL);
    attn_tc_kernel<<<gAtt, 128>>>(qkv, qkv + D_MODEL, qkv + 2 * D_MODEL, af,
                                  3 * D_MODEL, 3 * D_MODEL, 1);
    tc_gemm<false, true, false><<<gD, 256>>>(af, wf + WO_OFF, Bv[3], x, x1, nullptr, N_ROWS, D_MODEL, D_MODEL);

    // ---- cross-attention block (fused KV) ----
    ln_f16_kernel<<<N_ROWS, 256>>>(x1, ln2_g, ln2_b, af);
    tc_gemm<false, false, true><<<gD, 256>>>(af, wf + CQ_OFF, Bv[4], nullptr, nullptr, ff, N_ROWS, D_MODEL, D_MODEL);
    tc_gemm<false, false, true><<<gKV, 256>>>(sf, wf + CK_OFF, bkv, nullptr, nullptr, qkv, N_ROWS, 2 * D_MODEL, D_MODEL);
    attn_tc_kernel<<<gAtt, 128>>>(ff, qkv, qkv + D_MODEL, af,
                                  D_MODEL, 2 * D_MODEL, 0);
    tc_gemm<false, true, false><<<gD, 256>>>(af, wf + CO_OFF, Bv[7], x1, x2, nullptr, N_ROWS, D_MODEL, D_MODEL);

    // ---- FFN block ----
    ln_f16_kernel<<<N_ROWS, 256>>>(x2, ln3_g, ln3_b, af);
    tc_gemm<true, false, true><<<gF1, 256>>>(af, wf + W1_OFF, ff_b1, nullptr, nullptr, ff, N_ROWS, DFF_, D_MODEL);
    tc_gemm<false, true, false><<<gD, 256>>>(ff, wf + W2_OFF, ff_b2, x2, out, nullptr, N_ROWS, D_MODEL, DFF_);
}

// round 12
// speedup vs baseline: 2.8966x; 1.0112x over previous
#include <cuda_runtime.h>
#include <cuda_fp16.h>
#include <math.h>
#include <cstdint>

// ---------------------------------------------------------------------------
// SpectroTFDecoder: pre-LN transformer decoder layer, fp32 I/O.
// GEMMs + attention on mma.sync fp16 tensor cores (fp32 accum).
// QKV projections fused (N=3072); cross K/V fused (N=2048).
// Attention: FA2 register scheme, V via ldmatrix.trans, cp.async K/V
// double buffering.
// Input order: 0 x, 1 src_x, 2 mask, 3 src_mask, 4-9 ln{1,2,3}_{g,b},
// 10-17 weights (sa_wq,sa_wk,sa_wv,sa_wo,ca_wq,ca_wk,ca_wv,ca_wo),
// 18-25 biases (same order), 26-29 ff_w1,ff_b1,ff_w2,ff_b2.
// ---------------------------------------------------------------------------

#define D_MODEL 1024
#define BATCH   4
#define TSEQ    1024
#define N_ROWS  (BATCH * TSEQ)
#define NHEAD   16
#define DHEAD   64
#define DFF_    4096
#define LN_EPS  1e-6f

// fp32 scratch (residual streams + fused biases)
__device__ float g_x1 [N_ROWS * D_MODEL];
__device__ float g_x2 [N_ROWS * D_MODEL];
__device__ float g_bqkv[3 * D_MODEL];
__device__ float g_bkv [2 * D_MODEL];

// fp16 scratch
#define WQ_OFF  0
#define WK_OFF  (1 << 20)
#define WV_OFF  (2 << 20)
#define WO_OFF  (3 << 20)
#define CQ_OFF  (4 << 20)
#define CK_OFF  (5 << 20)
#define CV_OFF  (6 << 20)
#define CO_OFF  (7 << 20)
#define W1_OFF  (8 << 20)
#define W2_OFF  (12 << 20)
__device__ __half g_wf16[16 << 20];   // weights (transposed [N,K])
__device__ __half g_af16[4 << 20];    // activation / ctx (D-wide)
__device__ __half g_sf16[4 << 20];    // src_x (persistent)
__device__ __half g_ff16[16 << 20];   // FF intermediate / ca-Q scratch
__device__ __half g_qkv [12 << 20];   // fused QKV [4096,3072] / ca-KV [4096,2048]

// ---------------------------------------------------------------------------
// asm helpers
// ---------------------------------------------------------------------------
__device__ __forceinline__ uint32_t smem_u32(const void* p) {
    uint32_t a;
    asm("{ .reg .u64 t; cvta.to.shared.u64 t, %1; cvt.u32.u64 %0, t; }"
        : "=r"(a) : "l"(p));
    return a;
}
__device__ __forceinline__ void ldm4(uint32_t* r, uint32_t a) {
    asm volatile("ldmatrix.sync.aligned.m8n8.x4.shared.b16 {%0,%1,%2,%3}, [%4];"
                 : "=r"(r[0]), "=r"(r[1]), "=r"(r[2]), "=r"(r[3]) : "r"(a));
}
__device__ __forceinline__ void ldm4t(uint32_t* r, uint32_t a) {
    asm volatile("ldmatrix.sync.aligned.m8n8.x4.trans.shared.b16 {%0,%1,%2,%3}, [%4];"
                 : "=r"(r[0]), "=r"(r[1]), "=r"(r[2]), "=r"(r[3]) : "r"(a));
}
__device__ __forceinline__ void mma16816(float* c, const uint32_t* a,
                                         const uint32_t* b) {
    asm volatile(
        "mma.sync.aligned.m16n8k16.row.col.f32.f16.f16.f32 "
        "{%0,%1,%2,%3},{%4,%5,%6,%7},{%8,%9},{%0,%1,%2,%3};"
        : "+f"(c[0]), "+f"(c[1]), "+f"(c[2]), "+f"(c[3])
        : "r"(a[0]), "r"(a[1]), "r"(a[2]), "r"(a[3]), "r"(b[0]), "r"(b[1]));
}
#define CPA16(dst, src) \
    asm volatile("cp.async.cg.shared.global [%0], [%1], 16;" :: "r"(dst), "l"(src))
#define CPA_COMMIT() asm volatile("cp.async.commit_group;" ::: "memory")
#define CPA_WAIT0()  asm volatile("cp.async.wait_group 0;"  ::: "memory")
#define CPA_WAIT1()  asm volatile("cp.async.wait_group 1;"  ::: "memory")

// ---------------------------------------------------------------------------
// f16 convert: fp32 -> fp16. n multiple of 1024.
// ---------------------------------------------------------------------------
__global__ __launch_bounds__(256)
void f16_kernel(const float* __restrict__ in, __half* __restrict__ o)
{
    const int i = (blockIdx.x * 256 + threadIdx.x) * 4;
    float4 a = *(const float4*)(in + i);
    *(__half2*)(o + i)     = __floats2half2_rn(a.x, a.y);
    *(__half2*)(o + i + 2) = __floats2half2_rn(a.z, a.w);
}

// ---------------------------------------------------------------------------
// bias concat (grid sized by total n)
// ---------------------------------------------------------------------------
__global__ __launch_bounds__(256)
void catbias_kernel(const float* __restrict__ b0, const float* __restrict__ b1,
                    const float* __restrict__ b2, float* __restrict__ o)
{
    const int i = blockIdx.x * 256 + threadIdx.x;
    const float* s = (i < 1024) ? b0 : ((i < 2048) ? b1 : b2);
    o[i] = s[i & 1023];
}

// ---------------------------------------------------------------------------
// batched transpose+convert for the 8 square weights
// ---------------------------------------------------------------------------
struct WPtrs { const float* p[8]; };

__global__ __launch_bounds__(256)
void tsplit8_kernel(WPtrs ws, __half* __restrict__ obase)
{
    __shared__ float t[32][33];
    const float* W = ws.p[blockIdx.z];
    __half* o = obase + ((size_t)blockIdx.z << 20);
    const int x = threadIdx.x & 31;
    const int y = threadIdx.x >> 5;
    const int k0 = blockIdx.y * 32;
    const int n0 = blockIdx.x * 32;
    #pragma unroll
    for (int r = y; r < 32; r += 8)
        t[r][x] = W[(size_t)(k0 + r) * D_MODEL + n0 + x];
    __syncthreads();
    #pragma unroll
    for (int r = y; r < 32; r += 8)
        o[(size_t)(n0 + r) * D_MODEL + k0 + x] = __float2half(t[x][r]);
}

__global__ __launch_bounds__(256)
void tsplit_kernel(const float* __restrict__ W, __half* __restrict__ o,
                   int K, int N)
{
    __shared__ float t[32][33];
    const int x = threadIdx.x & 31;
    const int y = threadIdx.x >> 5;
    const int k0 = blockIdx.y * 32;
    const int n0 = blockIdx.x * 32;
    #pragma unroll
    for (int r = y; r < 32; r += 8)
        t[r][x] = W[(size_t)(k0 + r) * N + n0 + x];
    __syncthreads();
    #pragma unroll
    for (int r = y; r < 32; r += 8)
        o[(size_t)(n0 + r) * K + k0 + x] = __float2half(t[x][r]);
}

// ---------------------------------------------------------------------------
// LayerNorm fused with fp16 output.
// ---------------------------------------------------------------------------
__global__ __launch_bounds__(256)
void ln_f16_kernel(const float* __restrict__ x, const float* __restrict__ g,
                   const float* __restrict__ bta, __half* __restrict__ o)
{
    const int row = blockIdx.x;
    const int t = threadIdx.x;
    const float* xr = x + (size_t)row * D_MODEL;
    float4 xv = *(const float4*)(xr + t * 4);

    float s = xv.x + xv.y + xv.z + xv.w;
    __shared__ float red[8];
    #pragma unroll
    for (int off = 16; off > 0; off >>= 1) s += __shfl_xor_sync(~0u, s, off);
    if ((t & 31) == 0) red[t >> 5] = s;
    __syncthreads();
    float tot = 0.f;
    #pragma unroll
    for (int i = 0; i < 8; i++) tot += red[i];
    const float mu = tot * (1.f / 1024.f);

    const float dx0 = xv.x - mu, dx1 = xv.y - mu, dx2 = xv.z - mu, dx3 = xv.w - mu;
    float sq = dx0*dx0 + dx1*dx1 + dx2*dx2 + dx3*dx3;
    #pragma unroll
    for (int off = 16; off > 0; off >>= 1) sq += __shfl_xor_sync(~0u, sq, off);
    __syncthreads();
    if ((t & 31) == 0) red[t >> 5] = sq;
    __syncthreads();
    float tot2 = 0.f;
    #pragma unroll
    for (int i = 0; i < 8; i++) tot2 += red[i];
    const float sigma = sqrtf(tot2 * (1.f / 1024.f));
    const float inv = 1.f / (sigma + LN_EPS);

    float4 gv = *(const float4*)(g + t * 4);
    float4 bv = *(const float4*)(bta + t * 4);
    float o0 = dx0 * inv * gv.x + bv.x;
    float o1 = dx1 * inv * gv.y + bv.y;
    float o2 = dx2 * inv * gv.z + bv.z;
    float o3 = dx3 * inv * gv.w + bv.w;

    const size_t off = (size_t)row * D_MODEL + t * 4;
    *(__half2*)(o + off)     = __floats2half2_rn(o0, o1);
    *(__half2*)(o + off + 2) = __floats2half2_rn(o2, o3);
}

// ---------------------------------------------------------------------------
// Tensor-core GEMM, fp16 single-MMA, register-staged double buffer.
// BM=BN=128, BK=32, 8 warps (2x4), warp tile 64x32.
// ---------------------------------------------------------------------------
#define TG_ROW 40
#define TG_TILE (128 * TG_ROW)

template<bool RELU, bool RES, bool F16OUT>
__global__ __launch_bounds__(256, 2)
void tc_gemm(const __half* __restrict__ Af, const __half* __restrict__ Bf,
             const float* __restrict__ bias, const float* __restrict__ res,
             float* __restrict__ C, __half* __restrict__ Cf,
             int M, int N, int K)
{
    __shared__ __half As[2][TG_TILE];
    __shared__ __half Bs[2][TG_TILE];
    const uint32_t sbA = smem_u32(&As[0][0]);
    const uint32_t sbB = smem_u32(&Bs[0][0]);
    const int tid = threadIdx.x;
    const int lane = tid & 31;
    const int wid = tid >> 5;
    const int wm = wid >> 2;
    const int wn = wid & 3;
    const int bm = blockIdx.y * 128;
    const int bn = blockIdx.x * 128;

    const int srow = tid >> 1;
    const int shalf = (tid & 1) * 16;
    const uint32_t so = (uint32_t)(srow * TG_ROW + shalf) * 2;

    const char* gA = (const char*)(Af + (size_t)(bm + srow) * K + shalf);
    const char* gB = (const char*)(Bf + (size_t)(bn + srow) * K + shalf);

    const uint32_t a_off = (uint32_t)((lane & 15) * TG_ROW * 2 + (lane >> 4) * 16);
    const uint32_t b_off = (uint32_t)((((lane >> 4) << 3) + (lane & 7)) * TG_ROW * 2
                                      + ((lane >> 3) & 1) * 16);
    uint32_t aAddr[4], bAddr[2];
    #pragma unroll
    for (int mt = 0; mt < 4; mt++)
        aAddr[mt] = sbA + (uint32_t)((wm * 64 + mt * 16) * TG_ROW * 2) + a_off;
    #pragma unroll
    for (int ng = 0; ng < 2; ng++)
        bAddr[ng] = sbB + (uint32_t)((wn * 32 + ng * 16) * TG_ROW * 2) + b_off;

    float acc[4][4][4];
    #pragma unroll
    for (int mt = 0; mt < 4; mt++)
        #pragma unroll
        for (int nt = 0; nt < 4; nt++)
            #pragma unroll
            for (int r = 0; r < 4; r++) acc[mt][nt][r] = 0.f;

    {
        char* tA = (char*)&As[0][0];
        char* tB = (char*)&Bs[0][0];
        *(uint4*)(tA + so)      = *(const uint4*)gA;
        *(uint4*)(tA + so + 16) = *(const uint4*)(gA + 16);
        *(uint4*)(tB + so)      = *(const uint4*)gB;
        *(uint4*)(tB + so + 16) = *(const uint4*)(gB + 16);
    }
    __syncthreads();

    const int nk = K >> 5;
    for (int kt = 0; kt < nk; kt++) {
        const int cur = kt & 1;
        const int nxt = cur ^ 1;
        const bool more = (kt + 1 < nk);
        uint4 pa0, pa1, pb0, pb1;
        if (more) {
            const int gb = (kt + 1) * 64;
            pa0 = *(const uint4*)(gA + gb);
            pa1 = *(const uint4*)(gA + gb + 16);
            pb0 = *(const uint4*)(gB + gb);
            pb1 = *(const uint4*)(gB + gb + 16);
        }

        const uint32_t stA = (uint32_t)cur * (TG_TILE * 2);
        #pragma unroll
        for (int ks = 0; ks < 2; ks++) {
            const uint32_t kb = stA + ks * 32;
            uint32_t ah[4][4], bh[2][4];
            #pragma unroll
            for (int mt = 0; mt < 4; mt++)
                ldm4(ah[mt], aAddr[mt] + kb);
            #pragma unroll
            for (int ng = 0; ng < 2; ng++)
                ldm4(bh[ng], bAddr[ng] + kb);
            #pragma unroll
            for (int mt = 0; mt < 4; mt++) {
                #pragma unroll
                for (int nt = 0; nt < 4; nt++) {
                    const int ng = nt >> 1;
                    const int hf = (nt & 1) * 2;
                    mma16816(acc[mt][nt], ah[mt], &bh[ng][hf]);
                }
            }
        }

        if (more) {
            char* tA = (char*)&As[nxt][0];
            char* tB = (char*)&Bs[nxt][0];
            *(uint4*)(tA + so)      = pa0;
            *(uint4*)(tA + so + 16) = pa1;
            *(uint4*)(tB + so)      = pb0;
            *(uint4*)(tB + so + 16) = pb1;
        }
        __syncthreads();
    }

    const int er = lane >> 2;
    const int ec = (lane & 3) * 2;
    #pragma unroll
    for (int mt = 0; mt < 4; mt++) {
        const int row0 = bm + wm * 64 + mt * 16 + er;
        #pragma unroll
        for (int nt = 0; nt < 4; nt++) {
            const int col = bn + wn * 32 + nt * 8 + ec;
            float2 bv = *(const float2*)(bias + col);
            float v0 = acc[mt][nt][0] + bv.x;
            float v1 = acc[mt][nt][1] + bv.y;
            float v2 = acc[mt][nt][2] + bv.x;
            float v3 = acc[mt][nt][3] + bv.y;
            if (RELU) {
                v0 = fmaxf(v0, 0.f); v1 = fmaxf(v1, 0.f);
                v2 = fmaxf(v2, 0.f); v3 = fmaxf(v3, 0.f);
            }
            if (RES) {
                float2 r0 = *(const float2*)(res + (size_t)row0 * N + col);
                float2 r1 = *(const float2*)(res + (size_t)(row0 + 8) * N + col);
                v0 += r0.x; v1 += r0.y; v2 += r1.x; v3 += r1.y;
            }
            if (F16OUT) {
                *(__half2*)(Cf + (size_t)row0 * N + col)       = __floats2half2_rn(v0, v1);
                *(__half2*)(Cf + (size_t)(row0 + 8) * N + col) = __floats2half2_rn(v2, v3);
            } else {
                float2 o0 = {v0, v1};
                float2 o1 = {v2, v3};
                *(float2*)(C + (size_t)row0 * N + col) = o0;
                *(float2*)(C + (size_t)(row0 + 8) * N + col) = o1;
            }
        }
    }
}

// ---------------------------------------------------------------------------
// fp16 tensor-core flash attention (FA2 register scheme) with cp.async
// double-buffered K/V staging. Block = 64 q-rows x (head, batch),
// 128 threads / 4 warps; warp owns 16 rows. Q fragments persistent in
// registers (prescaled by 1/8); K/V staged natural; V via ldmatrix.trans.
// ---------------------------------------------------------------------------
#define QKST 72   // smem row stride in halves (144 B, conflict-free)

__global__ __launch_bounds__(128)
void attn_tc_kernel(const __half* __restrict__ Qf, const __half* __restrict__ Kf,
                    const __half* __restrict__ Vf, __half* __restrict__ Of,
                    int ldq, int ldkv, int causal)
{
    __shared__ __half Qs[64 * QKST];
    __shared__ __half Ks[2][64 * QKST];
    __shared__ __half Vs[2][64 * QKST];
    const int qt = blockIdx.x;
    const int h  = blockIdx.y;
    const int b  = blockIdx.z;
    const int tid = threadIdx.x;
    const int lane = tid & 31;
    const int wid = tid >> 5;
    const size_t qrow0 = (size_t)b * TSEQ;

    // staging address components (K/V)
    const int sr = tid >> 1;
    const int shoff = (tid & 1) * 32;
    const uint32_t ksm[2] = {smem_u32(&Ks[0][0]), smem_u32(&Ks[1][0])};
    const uint32_t vsm[2] = {smem_u32(&Vs[0][0]), smem_u32(&Vs[1][0])};
    const uint32_t srowoff = (uint32_t)(sr * QKST + shoff) * 2;

    const int ktEnd = causal ? qt : (TSEQ / 64 - 1);

    // issue cp.async for tile kt into buffer s
    auto issue_kv = [&](int s, int kt) {
        const size_t goff = (qrow0 + kt * 64 + sr) * (size_t)ldkv + h * DHEAD + shoff;
        const char* kg = (const char*)(Kf + goff);
        const char* vg = (const char*)(Vf + goff);
        const uint32_t kd = ksm[s] + srowoff;
        const uint32_t vd = vsm[s] + srowoff;
        CPA16(kd,      kg);
        CPA16(kd + 16, kg + 16);
        CPA16(kd + 32, kg + 32);
        CPA16(kd + 48, kg + 48);
        CPA16(vd,      vg);
        CPA16(vd + 16, vg + 16);
        CPA16(vd + 32, vg + 32);
        CPA16(vd + 48, vg + 48);
    };

    // prologue: start tile 0 load, then stage Q while it flies
    issue_kv(0, 0);
    CPA_COMMIT();
    {
        const __half2 sc = __floats2half2_rn(0.125f, 0.125f);
        const __half2* src = (const __half2*)(Qf + (qrow0 + qt * 64 + sr) * ldq
                                              + h * DHEAD + shoff);
        __half2* dst = (__half2*)(Qs + sr * QKST + shoff);
        #pragma unroll
        for (int i = 0; i < 16; i++) dst[i] = __hmul2(src[i], sc);
    }
    __syncthreads();

    const uint32_t a_off = (uint32_t)((lane & 15) * (QKST * 2) + (lane >> 4) * 16);
    const uint32_t b_off = (uint32_t)((((lane >> 4) << 3) + (lane & 7)) * (QKST * 2)
                                      + ((lane >> 3) & 1) * 16);

    // persistent Q fragments
    uint32_t qfr[4][4];
    {
        const uint32_t qa = smem_u32(Qs) + (uint32_t)(wid * 16) * (QKST * 2) + a_off;
        #pragma unroll
        for (int ks = 0; ks < 4; ks++) ldm4(qfr[ks], qa + ks * 32);
    }

    float m0 = -INFINITY, m1 = -INFINITY, l0 = 0.f, l1 = 0.f;
    float ao[8][4];
    #pragma unroll
    for (int nt = 0; nt < 8; nt++)
        #pragma unroll
        for (int r = 0; r < 4; r++) ao[nt][r] = 0.f;

    const int gr = lane >> 2;
    const int gc = (lane & 3) * 2;
    const int row0 = qt * 64 + wid * 16 + gr;
    const int row1 = row0 + 8;

    for (int kt = 0; kt <= ktEnd; kt++) {
        const int buf = kt & 1;
        const bool more = (kt + 1 <= ktEnd);
        if (more) issue_kv(buf ^ 1, kt + 1);
        CPA_COMMIT();
        if (more) { CPA_WAIT1(); } else { CPA_WAIT0(); }
        __syncthreads();   // tile kt visible to all threads

        const uint32_t kbase = ksm[buf];
        const uint32_t vbase = vsm[buf];

        // S = Q @ K^T
        float s[8][4];
        #pragma unroll
        for (int nt = 0; nt < 8; nt++)
            #pragma unroll
            for (int r = 0; r < 4; r++) s[nt][r] = 0.f;
        #pragma unroll
        for (int g = 0; g < 4; g++) {
            #pragma unroll
            for (int ks = 0; ks < 4; ks++) {
                uint32_t bh[4];
                ldm4(bh, kbase + (uint32_t)(g * 16) * (QKST * 2) + b_off + ks * 32);
                mma16816(s[2 * g],     qfr[ks], &bh[0]);
                mma16816(s[2 * g + 1], qfr[ks], &bh[2]);
            }
        }

        // causal mask + online softmax
        const bool diag = causal && (kt == qt);
        float rmax0 = -INFINITY, rmax1 = -INFINITY;
        #pragma unroll
        for (int nt = 0; nt < 8; nt++) {
            if (diag) {
                const int c0 = kt * 64 + nt * 8 + gc;
                if (c0 > row0)     s[nt][0] = -INFINITY;
                if (c0 + 1 > row0) s[nt][1] = -INFINITY;
                if (c0 > row1)     s[nt][2] = -INFINITY;
                if (c0 + 1 > row1) s[nt][3] = -INFINITY;
            }
            rmax0 = fmaxf(rmax0, fmaxf(s[nt][0], s[nt][1]));
            rmax1 = fmaxf(rmax1, fmaxf(s[nt][2], s[nt][3]));
        }
        rmax0 = fmaxf(rmax0, __shfl_xor_sync(~0u, rmax0, 1));
        rmax0 = fmaxf(rmax0, __shfl_xor_sync(~0u, rmax0, 2));
        rmax1 = fmaxf(rmax1, __shfl_xor_sync(~0u, rmax1, 1));
        rmax1 = fmaxf(rmax1, __shfl_xor_sync(~0u, rmax1, 2));

        const float mn0 = fmaxf(m0, rmax0);
        const float mn1 = fmaxf(m1, rmax1);
        const float corr0 = __expf(m0 - mn0);
        const float corr1 = __expf(m1 - mn1);
        float rs0 = 0.f, rs1 = 0.f;
        uint32_t pf[8][2];
        #pragma unroll
        for (int nt = 0; nt < 8; nt++) {
            const float p0 = __expf(s[nt][0] - mn0);
            const float p1 = __expf(s[nt][1] - mn0);
            const float p2 = __expf(s[nt][2] - mn1);
            const float p3 = __expf(s[nt][3] - mn1);
            rs0 += p0 + p1;
            rs1 += p2 + p3;
            __half2 h01 = __floats2half2_rn(p0, p1);
            __half2 h23 = __floats2half2_rn(p2, p3);
            pf[nt][0] = *(uint32_t*)&h01;
            pf[nt][1] = *(uint32_t*)&h23;
        }
        rs0 += __shfl_xor_sync(~0u, rs0, 1);
        rs0 += __shfl_xor_sync(~0u, rs0, 2);
        rs1 += __shfl_xor_sync(~0u, rs1, 1);
        rs1 += __shfl_xor_sync(~0u, rs1, 2);
        l0 = l0 * corr0 + rs0;
        l1 = l1 * corr1 + rs1;
        m0 = mn0;
        m1 = mn1;
        #pragma unroll
        for (int nt = 0; nt < 8; nt++) {
            ao[nt][0] *= corr0; ao[nt][1] *= corr0;
            ao[nt][2] *= corr1; ao[nt][3] *= corr1;
        }

        // O += P @ V (V^T fragments via ldmatrix.trans)
        #pragma unroll
        for (int kc = 0; kc < 4; kc++) {
            uint32_t pa[4] = {pf[2 * kc][0], pf[2 * kc][1],
                              pf[2 * kc + 1][0], pf[2 * kc + 1][1]};
            const uint32_t vrow = vbase + (uint32_t)(kc * 16) * (QKST * 2) + a_off;
            #pragma unroll
            for (int g = 0; g < 4; g++) {
                uint32_t bv[4];
                ldm4t(bv, vrow + g * 32);
                mma16816(ao[2 * g],     pa, &bv[0]);
                mma16816(ao[2 * g + 1], pa, &bv[2]);
            }
        }
        __syncthreads();   // everyone done reading buf before it is re-filled
    }

    // epilogue (output stride = D_MODEL)
    const float inv0 = 1.f / l0;
    const float inv1 = 1.f / l1;
    const size_t o0 = (qrow0 + row0) * D_MODEL + h * DHEAD;
    const size_t o1 = (qrow0 + row1) * D_MODEL + h * DHEAD;
    #pragma unroll
    for (int nt = 0; nt < 8; nt++) {
        const int col = nt * 8 + gc;
        *(__half2*)(Of + o0 + col) = __floats2half2_rn(ao[nt][0] * inv0, ao[nt][1] * inv0);
        *(__half2*)(Of + o1 + col) = __floats2half2_rn(ao[nt][2] * inv1, ao[nt][3] * inv1);
    }
}

// ---------------------------------------------------------------------------
// Host orchestration
// ---------------------------------------------------------------------------
extern "C" void kernel_launch(void* const* d_in, const int* in_sizes, int n_in,
                              void* d_out, int out_size)
{
    (void)in_sizes; (void)n_in; (void)out_size;
    const float* x     = (const float*)d_in[0];
    const float* src_x = (const float*)d_in[1];
    const float* ln1_g = (const float*)d_in[4];
    const float* ln1_b = (const float*)d_in[5];
    const float* ln2_g = (const float*)d_in[6];
    const float* ln2_b = (const float*)d_in[7];
    const float* ln3_g = (const float*)d_in[8];
    const float* ln3_b = (const float*)d_in[9];
    const float* W[8];
    for (int i = 0; i < 8; i++) W[i] = (const float*)d_in[10 + i];
    const float* Bv[8];
    for (int i = 0; i < 8; i++) Bv[i] = (const float*)d_in[18 + i];
    const float* ff_w1 = (const float*)d_in[26];
    const float* ff_b1 = (const float*)d_in[27];
    const float* ff_w2 = (const float*)d_in[28];
    const float* ff_b2 = (const float*)d_in[29];
    float* out = (float*)d_out;

    float *x1, *x2, *bqkv, *bkv;
    cudaGetSymbolAddress((void**)&x1, g_x1);
    cudaGetSymbolAddress((void**)&x2, g_x2);
    cudaGetSymbolAddress((void**)&bqkv, g_bqkv);
    cudaGetSymbolAddress((void**)&bkv,  g_bkv);
    __half *wf, *af, *sf, *ff, *qkv;
    cudaGetSymbolAddress((void**)&wf,  g_wf16);
    cudaGetSymbolAddress((void**)&af,  g_af16);
    cudaGetSymbolAddress((void**)&sf,  g_sf16);
    cudaGetSymbolAddress((void**)&ff,  g_ff16);
    cudaGetSymbolAddress((void**)&qkv, g_qkv);

    const dim3 gQKV(3 * D_MODEL / 128, N_ROWS / 128);   // (24, 32)
    const dim3 gKV (2 * D_MODEL / 128, N_ROWS / 128);   // (16, 32)
    const dim3 gD  (D_MODEL / 128, N_ROWS / 128);       // (8, 32)
    const dim3 gF1 (DFF_   / 128, N_ROWS / 128);        // (32, 32)
    const dim3 gAtt(TSEQ / 64, NHEAD, BATCH);

    // ---- prep (5 launches so QKV gemm lands at ncu index 5) ----
    {
        WPtrs ws;
        for (int i = 0; i < 8; i++) ws.p[i] = W[i];
        dim3 g8(D_MODEL / 32, D_MODEL / 32, 8);
        tsplit8_kernel<<<g8, 256>>>(ws, wf);                       // 0
        dim3 g1(DFF_ / 32, D_MODEL / 32);
        tsplit_kernel<<<g1, 256>>>(ff_w1, wf + W1_OFF, D_MODEL, DFF_);   // 1
        dim3 g2(D_MODEL / 32, DFF_ / 32);
        tsplit_kernel<<<g2, 256>>>(ff_w2, wf + W2_OFF, DFF_, D_MODEL);   // 2
    }
    catbias_kernel<<<12, 256>>>(Bv[0], Bv[1], Bv[2], bqkv);        // 3
    ln_f16_kernel<<<N_ROWS, 256>>>(x, ln1_g, ln1_b, af);           // 4

    // ---- self-attention block (fused QKV) ----
    tc_gemm<false, false, true><<<gQKV, 256>>>(af, wf + WQ_OFF, bqkv, nullptr, nullptr, qkv, N_ROWS, 3 * D_MODEL, D_MODEL);   // 5 (ncu)
    attn_tc_kernel<<<gAtt, 128>>>(qkv, qkv + D_MODEL, qkv + 2 * D_MODEL, af,
                                  3 * D_MODEL, 3 * D_MODEL, 1);
    tc_gemm<false, true, false><<<gD, 256>>>(af, wf + WO_OFF, Bv[3], x, x1, nullptr, N_ROWS, D_MODEL, D_MODEL);

    // ---- cross-attention block (fused KV) ----
    catbias_kernel<<<8, 256>>>(Bv[5], Bv[6], Bv[6], bkv);
    f16_kernel<<<(N_ROWS * D_MODEL) / 1024, 256>>>(src_x, sf);
    ln_f16_kernel<<<N_ROWS, 256>>>(x1, ln2_g, ln2_b, af);
    tc_gemm<false, false, true><<<gD, 256>>>(af, wf + CQ_OFF, Bv[4], nullptr, nullptr, ff, N_ROWS, D_MODEL, D_MODEL);
    tc_gemm<false, false, true><<<gKV, 256>>>(sf, wf + CK_OFF, bkv, nullptr, nullptr, qkv, N_ROWS, 2 * D_MODEL, D_MODEL);
    attn_tc_kernel<<<gAtt, 128>>>(ff, qkv, qkv + D_MODEL, af,
                                  D_MODEL, 2 * D_MODEL, 0);
    tc_gemm<false, true, false><<<gD, 256>>>(af, wf + CO_OFF, Bv[7], x1, x2, nullptr, N_ROWS, D_MODEL, D_MODEL);

    // ---- FFN block ----
    ln_f16_kernel<<<N_ROWS, 256>>>(x2, ln3_g, ln3_b, af);
    tc_gemm<true, false, true><<<gF1, 256>>>(af, wf + W1_OFF, ff_b1, nullptr, nullptr, ff, N_ROWS, DFF_, D_MODEL);
    tc_gemm<false, true, false><<<gD, 256>>>(ff, wf + W2_OFF, ff_b2, x2, out, nullptr, N_ROWS, D_MODEL, DFF_);
}

// round 13
// speedup vs baseline: 3.2098x; 1.1081x over previous
#include <cuda_runtime.h>
#include <cuda_fp16.h>
#include <math.h>
#include <cstdint>

// ---------------------------------------------------------------------------
// SpectroTFDecoder: pre-LN transformer decoder layer, fp32 I/O.
// GEMMs + attention on mma.sync fp16 tensor cores (fp32 accum).
// Weights kept in NATURAL [K,N] layout (no transpose prep); B operand
// consumed via ldmatrix.trans. QKV fused (N=3072); cross K/V fused (N=2048).
// Attention: FA2 register scheme, V via ldmatrix.trans, cp.async K/V
// double buffering.
// Input order: 0 x, 1 src_x, 2 mask, 3 src_mask, 4-9 ln{1,2,3}_{g,b},
// 10-17 weights (sa_wq,sa_wk,sa_wv,sa_wo,ca_wq,ca_wk,ca_wv,ca_wo),
// 18-25 biases (same order), 26-29 ff_w1,ff_b1,ff_w2,ff_b2.
// ---------------------------------------------------------------------------

#define D_MODEL 1024
#define BATCH   4
#define TSEQ    1024
#define N_ROWS  (BATCH * TSEQ)
#define NHEAD   16
#define DHEAD   64
#define DFF_    4096
#define LN_EPS  1e-6f

// fp32 scratch (residual streams + fused biases)
__device__ float g_x1 [N_ROWS * D_MODEL];
__device__ float g_x2 [N_ROWS * D_MODEL];
__device__ float g_bqkv[3 * D_MODEL];
__device__ float g_bkv [2 * D_MODEL];

// fp16 scratch (weights natural [K,N], 1M-half segments for square ones)
#define WQ_OFF  0
#define WK_OFF  (1 << 20)
#define WV_OFF  (2 << 20)
#define WO_OFF  (3 << 20)
#define CQ_OFF  (4 << 20)
#define CK_OFF  (5 << 20)
#define CV_OFF  (6 << 20)
#define CO_OFF  (7 << 20)
#define W1_OFF  (8 << 20)
#define W2_OFF  (12 << 20)
__device__ __half g_wf16[16 << 20];   // weights, natural layout
__device__ __half g_af16[4 << 20];    // activation / ctx (D-wide)
__device__ __half g_sf16[4 << 20];    // src_x (persistent)
__device__ __half g_ff16[16 << 20];   // FF intermediate / ca-Q scratch
__device__ __half g_qkv [12 << 20];   // fused QKV / ca-KV

// ---------------------------------------------------------------------------
// asm helpers
// ---------------------------------------------------------------------------
__device__ __forceinline__ uint32_t smem_u32(const void* p) {
    uint32_t a;
    asm("{ .reg .u64 t; cvta.to.shared.u64 t, %1; cvt.u32.u64 %0, t; }"
        : "=r"(a) : "l"(p));
    return a;
}
__device__ __forceinline__ void ldm4(uint32_t* r, uint32_t a) {
    asm volatile("ldmatrix.sync.aligned.m8n8.x4.shared.b16 {%0,%1,%2,%3}, [%4];"
                 : "=r"(r[0]), "=r"(r[1]), "=r"(r[2]), "=r"(r[3]) : "r"(a));
}
__device__ __forceinline__ void ldm4t(uint32_t* r, uint32_t a) {
    asm volatile("ldmatrix.sync.aligned.m8n8.x4.trans.shared.b16 {%0,%1,%2,%3}, [%4];"
                 : "=r"(r[0]), "=r"(r[1]), "=r"(r[2]), "=r"(r[3]) : "r"(a));
}
__device__ __forceinline__ void mma16816(float* c, const uint32_t* a,
                                         const uint32_t* b) {
    asm volatile(
        "mma.sync.aligned.m16n8k16.row.col.f32.f16.f16.f32 "
        "{%0,%1,%2,%3},{%4,%5,%6,%7},{%8,%9},{%0,%1,%2,%3};"
        : "+f"(c[0]), "+f"(c[1]), "+f"(c[2]), "+f"(c[3])
        : "r"(a[0]), "r"(a[1]), "r"(a[2]), "r"(a[3]), "r"(b[0]), "r"(b[1]));
}
#define CPA16(dst, src) \
    asm volatile("cp.async.cg.shared.global [%0], [%1], 16;" :: "r"(dst), "l"(src))
#define CPA_COMMIT() asm volatile("cp.async.commit_group;" ::: "memory")
#define CPA_WAIT0()  asm volatile("cp.async.wait_group 0;"  ::: "memory")
#define CPA_WAIT1()  asm volatile("cp.async.wait_group 1;"  ::: "memory")

// ---------------------------------------------------------------------------
// batched elementwise fp32 -> fp16 convert: 20 slices of 1M elements.
// Covers 8 square weights (1 slice each), ff_w1 (4), ff_w2 (4), src_x (4).
// ---------------------------------------------------------------------------
struct CvtJob { const float* s[20]; __half* d[20]; };

__global__ __launch_bounds__(256)
void cvt_kernel(CvtJob j)
{
    const float* s = j.s[blockIdx.z];
    __half* d = j.d[blockIdx.z];
    const int i = (blockIdx.x * 256 + threadIdx.x) * 4;
    float4 a = *(const float4*)(s + i);
    *(__half2*)(d + i)     = __floats2half2_rn(a.x, a.y);
    *(__half2*)(d + i + 2) = __floats2half2_rn(a.z, a.w);
}

// ---------------------------------------------------------------------------
// bias concat (grid sized by total n)
// ---------------------------------------------------------------------------
__global__ __launch_bounds__(256)
void catbias_kernel(const float* __restrict__ b0, const float* __restrict__ b1,
                    const float* __restrict__ b2, float* __restrict__ o)
{
    const int i = blockIdx.x * 256 + threadIdx.x;
    const float* s = (i < 1024) ? b0 : ((i < 2048) ? b1 : b2);
    o[i] = s[i & 1023];
}

// ---------------------------------------------------------------------------
// LayerNorm fused with fp16 output.
// ---------------------------------------------------------------------------
__global__ __launch_bounds__(256)
void ln_f16_kernel(const float* __restrict__ x, const float* __restrict__ g,
                   const float* __restrict__ bta, __half* __restrict__ o)
{
    const int row = blockIdx.x;
    const int t = threadIdx.x;
    const float* xr = x + (size_t)row * D_MODEL;
    float4 xv = *(const float4*)(xr + t * 4);

    float s = xv.x + xv.y + xv.z + xv.w;
    __shared__ float red[8];
    #pragma unroll
    for (int off = 16; off > 0; off >>= 1) s += __shfl_xor_sync(~0u, s, off);
    if ((t & 31) == 0) red[t >> 5] = s;
    __syncthreads();
    float tot = 0.f;
    #pragma unroll
    for (int i = 0; i < 8; i++) tot += red[i];
    const float mu = tot * (1.f / 1024.f);

    const float dx0 = xv.x - mu, dx1 = xv.y - mu, dx2 = xv.z - mu, dx3 = xv.w - mu;
    float sq = dx0*dx0 + dx1*dx1 + dx2*dx2 + dx3*dx3;
    #pragma unroll
    for (int off = 16; off > 0; off >>= 1) sq += __shfl_xor_sync(~0u, sq, off);
    __syncthreads();
    if ((t & 31) == 0) red[t >> 5] = sq;
    __syncthreads();
    float tot2 = 0.f;
    #pragma unroll
    for (int i = 0; i < 8; i++) tot2 += red[i];
    const float sigma = sqrtf(tot2 * (1.f / 1024.f));
    const float inv = 1.f / (sigma + LN_EPS);

    float4 gv = *(const float4*)(g + t * 4);
    float4 bv = *(const float4*)(bta + t * 4);
    float o0 = dx0 * inv * gv.x + bv.x;
    float o1 = dx1 * inv * gv.y + bv.y;
    float o2 = dx2 * inv * gv.z + bv.z;
    float o3 = dx3 * inv * gv.w + bv.w;

    const size_t off = (size_t)row * D_MODEL + t * 4;
    *(__half2*)(o + off)     = __floats2half2_rn(o0, o1);
    *(__half2*)(o + off + 2) = __floats2half2_rn(o2, o3);
}

// ---------------------------------------------------------------------------
// Tensor-core GEMM, fp16 single-MMA, register-staged double buffer.
// A [M,K] fp16 row-major; B NATURAL [K,N-segment] fp16 row-major, consumed
// via ldmatrix.trans (fragment mapping identical to the attention P*V path).
// Segmented B supports fused N: segment = bn >> seg_shift, row length
// 1<<seg_shift, segments seg_stride halves apart.
// BM=BN=128, BK=32, 8 warps (2x4), warp tile 64x32.
// ---------------------------------------------------------------------------
#define TG_ROW 40
#define TG_TILE (128 * TG_ROW)
#define TB_ROW 136
#define TB_TILE (32 * TB_ROW)

template<bool RELU, bool RES, bool F16OUT>
__global__ __launch_bounds__(256, 2)
void tc_gemm(const __half* __restrict__ Af, const __half* __restrict__ Bf,
             int seg_shift, size_t seg_stride,
             const float* __restrict__ bias, const float* __restrict__ res,
             float* __restrict__ C, __half* __restrict__ Cf,
             int M, int N, int K)
{
    __shared__ __half As[2][TG_TILE];
    __shared__ __half Bs[2][TB_TILE];
    const uint32_t sbA = smem_u32(&As[0][0]);
    const uint32_t sbB = smem_u32(&Bs[0][0]);
    const int tid = threadIdx.x;
    const int lane = tid & 31;
    const int wid = tid >> 5;
    const int wm = wid >> 2;
    const int wn = wid & 3;
    const int bm = blockIdx.y * 128;
    const int bn = blockIdx.x * 128;

    const int ld_b = 1 << seg_shift;
    const __half* Bseg = Bf + (size_t)(bn >> seg_shift) * seg_stride;
    const int bn_l = bn & (ld_b - 1);

    // A staging: thread -> (row 0..127, 16-elem half)
    const int srow = tid >> 1;
    const int shalf = (tid & 1) * 16;
    const uint32_t soA = (uint32_t)(srow * TG_ROW + shalf) * 2;
    const char* gA = (const char*)(Af + (size_t)(bm + srow) * K + shalf);

    // B staging: thread -> (k-row 0..31, 16-elem col chunk)
    const int brow = tid >> 3;
    const int bcol = (tid & 7) * 16;
    const uint32_t soB = (uint32_t)(brow * TB_ROW + bcol) * 2;
    const char* gB = (const char*)(Bseg + (size_t)brow * ld_b + bn_l + bcol);
    const size_t bstep = (size_t)32 * ld_b * 2;   // bytes per k-tile

    const uint32_t a_off = (uint32_t)((lane & 15) * TG_ROW * 2 + (lane >> 4) * 16);
    const uint32_t b_off = (uint32_t)((lane & 15) * TB_ROW * 2 + (lane >> 4) * 16);
    uint32_t aAddr[4], bAddr[2];
    #pragma unroll
    for (int mt = 0; mt < 4; mt++)
        aAddr[mt] = sbA + (uint32_t)((wm * 64 + mt * 16) * TG_ROW * 2) + a_off;
    #pragma unroll
    for (int ng = 0; ng < 2; ng++)
        bAddr[ng] = sbB + (uint32_t)((wn * 32 + ng * 16) * 2) + b_off;

    float acc[4][4][4];
    #pragma unroll
    for (int mt = 0; mt < 4; mt++)
        #pragma unroll
        for (int nt = 0; nt < 4; nt++)
            #pragma unroll
            for (int r = 0; r < 4; r++) acc[mt][nt][r] = 0.f;

    {
        char* tA = (char*)&As[0][0];
        char* tB = (char*)&Bs[0][0];
        *(uint4*)(tA + soA)      = *(const uint4*)gA;
        *(uint4*)(tA + soA + 16) = *(const uint4*)(gA + 16);
        *(uint4*)(tB + soB)      = *(const uint4*)gB;
        *(uint4*)(tB + soB + 16) = *(const uint4*)(gB + 16);
    }
    __syncthreads();

    const int nk = K >> 5;
    for (int kt = 0; kt < nk; kt++) {
        const int cur = kt & 1;
        const int nxt = cur ^ 1;
        const bool more = (kt + 1 < nk);
        uint4 pa0, pa1, pb0, pb1;
        if (more) {
            pa0 = *(const uint4*)(gA + (kt + 1) * 64);
            pa1 = *(const uint4*)(gA + (kt + 1) * 64 + 16);
            pb0 = *(const uint4*)(gB + (size_t)(kt + 1) * bstep);
            pb1 = *(const uint4*)(gB + (size_t)(kt + 1) * bstep + 16);
        }

        const uint32_t stA = (uint32_t)cur * (TG_TILE * 2);
        const uint32_t stB = (uint32_t)cur * (TB_TILE * 2);
        #pragma unroll
        for (int ks = 0; ks < 2; ks++) {
            const uint32_t kbA = stA + ks * 32;
            const uint32_t kbB = stB + (uint32_t)(ks * 16 * TB_ROW * 2);
            uint32_t ah[4][4], bt[2][4];
            #pragma unroll
            for (int mt = 0; mt < 4; mt++)
                ldm4(ah[mt], aAddr[mt] + kbA);
            #pragma unroll
            for (int ng = 0; ng < 2; ng++)
                ldm4t(bt[ng], bAddr[ng] + kbB);
            #pragma unroll
            for (int mt = 0; mt < 4; mt++) {
                #pragma unroll
                for (int nt = 0; nt < 4; nt++) {
                    const int ng = nt >> 1;
                    const int hf = (nt & 1) * 2;
                    mma16816(acc[mt][nt], ah[mt], &bt[ng][hf]);
                }
            }
        }

        if (more) {
            char* tA = (char*)&As[nxt][0];
            char* tB = (char*)&Bs[nxt][0];
            *(uint4*)(tA + soA)      = pa0;
            *(uint4*)(tA + soA + 16) = pa1;
            *(uint4*)(tB + soB)      = pb0;
            *(uint4*)(tB + soB + 16) = pb1;
        }
        __syncthreads();
    }

    const int er = lane >> 2;
    const int ec = (lane & 3) * 2;
    #pragma unroll
    for (int mt = 0; mt < 4; mt++) {
        const int row0 = bm + wm * 64 + mt * 16 + er;
        #pragma unroll
        for (int nt = 0; nt < 4; nt++) {
            const int col = bn + wn * 32 + nt * 8 + ec;
            float2 bv = *(const float2*)(bias + col);
            float v0 = acc[mt][nt][0] + bv.x;
            float v1 = acc[mt][nt][1] + bv.y;
            float v2 = acc[mt][nt][2] + bv.x;
            float v3 = acc[mt][nt][3] + bv.y;
            if (RELU) {
                v0 = fmaxf(v0, 0.f); v1 = fmaxf(v1, 0.f);
                v2 = fmaxf(v2, 0.f); v3 = fmaxf(v3, 0.f);
            }
            if (RES) {
                float2 r0 = *(const float2*)(res + (size_t)row0 * N + col);
                float2 r1 = *(const float2*)(res + (size_t)(row0 + 8) * N + col);
                v0 += r0.x; v1 += r0.y; v2 += r1.x; v3 += r1.y;
            }
            if (F16OUT) {
                *(__half2*)(Cf + (size_t)row0 * N + col)       = __floats2half2_rn(v0, v1);
                *(__half2*)(Cf + (size_t)(row0 + 8) * N + col) = __floats2half2_rn(v2, v3);
            } else {
                float2 o0 = {v0, v1};
                float2 o1 = {v2, v3};
                *(float2*)(C + (size_t)row0 * N + col) = o0;
                *(float2*)(C + (size_t)(row0 + 8) * N + col) = o1;
            }
        }
    }
}

// ---------------------------------------------------------------------------
// fp16 tensor-core flash attention (FA2 register scheme) with cp.async
// double-buffered K/V staging (round-12 version, unchanged).
// ---------------------------------------------------------------------------
#define QKST 72

__global__ __launch_bounds__(128)
void attn_tc_kernel(const __half* __restrict__ Qf, const __half* __restrict__ Kf,
                    const __half* __restrict__ Vf, __half* __restrict__ Of,
                    int ldq, int ldkv, int causal)
{
    __shared__ __half Qs[64 * QKST];
    __shared__ __half Ks[2][64 * QKST];
    __shared__ __half Vs[2][64 * QKST];
    const int qt = blockIdx.x;
    const int h  = blockIdx.y;
    const int b  = blockIdx.z;
    const int tid = threadIdx.x;
    const int lane = tid & 31;
    const int wid = tid >> 5;
    const size_t qrow0 = (size_t)b * TSEQ;

    const int sr = tid >> 1;
    const int shoff = (tid & 1) * 32;
    const uint32_t ksm[2] = {smem_u32(&Ks[0][0]), smem_u32(&Ks[1][0])};
    const uint32_t vsm[2] = {smem_u32(&Vs[0][0]), smem_u32(&Vs[1][0])};
    const uint32_t srowoff = (uint32_t)(sr * QKST + shoff) * 2;

    const int ktEnd = causal ? qt : (TSEQ / 64 - 1);

    auto issue_kv = [&](int s, int kt) {
        const size_t goff = (qrow0 + kt * 64 + sr) * (size_t)ldkv + h * DHEAD + shoff;
        const char* kg = (const char*)(Kf + goff);
        const char* vg = (const char*)(Vf + goff);
        const uint32_t kd = ksm[s] + srowoff;
        const uint32_t vd = vsm[s] + srowoff;
        CPA16(kd,      kg);
        CPA16(kd + 16, kg + 16);
        CPA16(kd + 32, kg + 32);
        CPA16(kd + 48, kg + 48);
        CPA16(vd,      vg);
        CPA16(vd + 16, vg + 16);
        CPA16(vd + 32, vg + 32);
        CPA16(vd + 48, vg + 48);
    };

    issue_kv(0, 0);
    CPA_COMMIT();
    {
        const __half2 sc = __floats2half2_rn(0.125f, 0.125f);
        const __half2* src = (const __half2*)(Qf + (qrow0 + qt * 64 + sr) * ldq
                                              + h * DHEAD + shoff);
        __half2* dst = (__half2*)(Qs + sr * QKST + shoff);
        #pragma unroll
        for (int i = 0; i < 16; i++) dst[i] = __hmul2(src[i], sc);
    }
    __syncthreads();

    const uint32_t a_off = (uint32_t)((lane & 15) * (QKST * 2) + (lane >> 4) * 16);
    const uint32_t b_off = (uint32_t)((((lane >> 4) << 3) + (lane & 7)) * (QKST * 2)
                                      + ((lane >> 3) & 1) * 16);

    uint32_t qfr[4][4];
    {
        const uint32_t qa = smem_u32(Qs) + (uint32_t)(wid * 16) * (QKST * 2) + a_off;
        #pragma unroll
        for (int ks = 0; ks < 4; ks++) ldm4(qfr[ks], qa + ks * 32);
    }

    float m0 = -INFINITY, m1 = -INFINITY, l0 = 0.f, l1 = 0.f;
    float ao[8][4];
    #pragma unroll
    for (int nt = 0; nt < 8; nt++)
        #pragma unroll
        for (int r = 0; r < 4; r++) ao[nt][r] = 0.f;

    const int gr = lane >> 2;
    const int gc = (lane & 3) * 2;
    const int row0 = qt * 64 + wid * 16 + gr;
    const int row1 = row0 + 8;

    for (int kt = 0; kt <= ktEnd; kt++) {
        const int buf = kt & 1;
        const bool more = (kt + 1 <= ktEnd);
        if (more) issue_kv(buf ^ 1, kt + 1);
        CPA_COMMIT();
        if (more) { CPA_WAIT1(); } else { CPA_WAIT0(); }
        __syncthreads();

        const uint32_t kbase = ksm[buf];
        const uint32_t vbase = vsm[buf];

        float s[8][4];
        #pragma unroll
        for (int nt = 0; nt < 8; nt++)
            #pragma unroll
            for (int r = 0; r < 4; r++) s[nt][r] = 0.f;
        #pragma unroll
        for (int g = 0; g < 4; g++) {
            #pragma unroll
            for (int ks = 0; ks < 4; ks++) {
                uint32_t bh[4];
                ldm4(bh, kbase + (uint32_t)(g * 16) * (QKST * 2) + b_off + ks * 32);
                mma16816(s[2 * g],     qfr[ks], &bh[0]);
                mma16816(s[2 * g + 1], qfr[ks], &bh[2]);
            }
        }

        const bool diag = causal && (kt == qt);
        float rmax0 = -INFINITY, rmax1 = -INFINITY;
        #pragma unroll
        for (int nt = 0; nt < 8; nt++) {
            if (diag) {
                const int c0 = kt * 64 + nt * 8 + gc;
                if (c0 > row0)     s[nt][0] = -INFINITY;
                if (c0 + 1 > row0) s[nt][1] = -INFINITY;
                if (c0 > row1)     s[nt][2] = -INFINITY;
                if (c0 + 1 > row1) s[nt][3] = -INFINITY;
            }
            rmax0 = fmaxf(rmax0, fmaxf(s[nt][0], s[nt][1]));
            rmax1 = fmaxf(rmax1, fmaxf(s[nt][2], s[nt][3]));
        }
        rmax0 = fmaxf(rmax0, __shfl_xor_sync(~0u, rmax0, 1));
        rmax0 = fmaxf(rmax0, __shfl_xor_sync(~0u, rmax0, 2));
        rmax1 = fmaxf(rmax1, __shfl_xor_sync(~0u, rmax1, 1));
        rmax1 = fmaxf(rmax1, __shfl_xor_sync(~0u, rmax1, 2));

        const float mn0 = fmaxf(m0, rmax0);
        const float mn1 = fmaxf(m1, rmax1);
        const float corr0 = __expf(m0 - mn0);
        const float corr1 = __expf(m1 - mn1);
        float rs0 = 0.f, rs1 = 0.f;
        uint32_t pf[8][2];
        #pragma unroll
        for (int nt = 0; nt < 8; nt++) {
            const float p0 = __expf(s[nt][0] - mn0);
            const float p1 = __expf(s[nt][1] - mn0);
            const float p2 = __expf(s[nt][2] - mn1);
            const float p3 = __expf(s[nt][3] - mn1);
            rs0 += p0 + p1;
            rs1 += p2 + p3;
            __half2 h01 = __floats2half2_rn(p0, p1);
            __half2 h23 = __floats2half2_rn(p2, p3);
            pf[nt][0] = *(uint32_t*)&h01;
            pf[nt][1] = *(uint32_t*)&h23;
        }
        rs0 += __shfl_xor_sync(~0u, rs0, 1);
        rs0 += __shfl_xor_sync(~0u, rs0, 2);
        rs1 += __shfl_xor_sync(~0u, rs1, 1);
        rs1 += __shfl_xor_sync(~0u, rs1, 2);
        l0 = l0 * corr0 + rs0;
        l1 = l1 * corr1 + rs1;
        m0 = mn0;
        m1 = mn1;
        #pragma unroll
        for (int nt = 0; nt < 8; nt++) {
            ao[nt][0] *= corr0; ao[nt][1] *= corr0;
            ao[nt][2] *= corr1; ao[nt][3] *= corr1;
        }

        #pragma unroll
        for (int kc = 0; kc < 4; kc++) {
            uint32_t pa[4] = {pf[2 * kc][0], pf[2 * kc][1],
                              pf[2 * kc + 1][0], pf[2 * kc + 1][1]};
            const uint32_t vrow = vbase + (uint32_t)(kc * 16) * (QKST * 2) + a_off;
            #pragma unroll
            for (int g = 0; g < 4; g++) {
                uint32_t bv[4];
                ldm4t(bv, vrow + g * 32);
                mma16816(ao[2 * g],     pa, &bv[0]);
                mma16816(ao[2 * g + 1], pa, &bv[2]);
            }
        }
        __syncthreads();
    }

    const float inv0 = 1.f / l0;
    const float inv1 = 1.f / l1;
    const size_t o0 = (qrow0 + row0) * D_MODEL + h * DHEAD;
    const size_t o1 = (qrow0 + row1) * D_MODEL + h * DHEAD;
    #pragma unroll
    for (int nt = 0; nt < 8; nt++) {
        const int col = nt * 8 + gc;
        *(__half2*)(Of + o0 + col) = __floats2half2_rn(ao[nt][0] * inv0, ao[nt][1] * inv0);
        *(__half2*)(Of + o1 + col) = __floats2half2_rn(ao[nt][2] * inv1, ao[nt][3] * inv1);
    }
}

// ---------------------------------------------------------------------------
// Host orchestration
// ---------------------------------------------------------------------------
extern "C" void kernel_launch(void* const* d_in, const int* in_sizes, int n_in,
                              void* d_out, int out_size)
{
    (void)in_sizes; (void)n_in; (void)out_size;
    const float* x     = (const float*)d_in[0];
    const float* src_x = (const float*)d_in[1];
    const float* ln1_g = (const float*)d_in[4];
    const float* ln1_b = (const float*)d_in[5];
    const float* ln2_g = (const float*)d_in[6];
    const float* ln2_b = (const float*)d_in[7];
    const float* ln3_g = (const float*)d_in[8];
    const float* ln3_b = (const float*)d_in[9];
    const float* W[8];
    for (int i = 0; i < 8; i++) W[i] = (const float*)d_in[10 + i];
    const float* Bv[8];
    for (int i = 0; i < 8; i++) Bv[i] = (const float*)d_in[18 + i];
    const float* ff_w1 = (const float*)d_in[26];
    const float* ff_b1 = (const float*)d_in[27];
    const float* ff_w2 = (const float*)d_in[28];
    const float* ff_b2 = (const float*)d_in[29];
    float* out = (float*)d_out;

    float *x1, *x2, *bqkv, *bkv;
    cudaGetSymbolAddress((void**)&x1, g_x1);
    cudaGetSymbolAddress((void**)&x2, g_x2);
    cudaGetSymbolAddress((void**)&bqkv, g_bqkv);
    cudaGetSymbolAddress((void**)&bkv,  g_bkv);
    __half *wf, *af, *sf, *ff, *qkv;
    cudaGetSymbolAddress((void**)&wf,  g_wf16);
    cudaGetSymbolAddress((void**)&af,  g_af16);
    cudaGetSymbolAddress((void**)&sf,  g_sf16);
    cudaGetSymbolAddress((void**)&ff,  g_ff16);
    cudaGetSymbolAddress((void**)&qkv, g_qkv);

    const dim3 gQKV(3 * D_MODEL / 128, N_ROWS / 128);
    const dim3 gKV (2 * D_MODEL / 128, N_ROWS / 128);
    const dim3 gD  (D_MODEL / 128, N_ROWS / 128);
    const dim3 gF1 (DFF_   / 128, N_ROWS / 128);
    const dim3 gAtt(TSEQ / 64, NHEAD, BATCH);
    const size_t SEG = (size_t)1 << 20;

    // ---- batched convert: 8 square weights + ff_w1 + ff_w2 + src_x ----
    {
        CvtJob j;
        for (int i = 0; i < 8; i++) { j.s[i] = W[i]; j.d[i] = wf + (i << 20); }
        for (int i = 0; i < 4; i++) {
            j.s[8  + i] = ff_w1 + i * (1 << 20); j.d[8  + i] = wf + W1_OFF + (i << 20);
            j.s[12 + i] = ff_w2 + i * (1 << 20); j.d[12 + i] = wf + W2_OFF + (i << 20);
            j.s[16 + i] = src_x + i * (1 << 20); j.d[16 + i] = sf + (i << 20);
        }
        dim3 gc(1024, 1, 20);
        cvt_kernel<<<gc, 256>>>(j);
    }
    catbias_kernel<<<12, 256>>>(Bv[0], Bv[1], Bv[2], bqkv);
    catbias_kernel<<<8, 256>>>(Bv[5], Bv[6], Bv[6], bkv);
    ln_f16_kernel<<<N_ROWS, 256>>>(x, ln1_g, ln1_b, af);

    // ---- self-attention block (fused QKV) ----
    tc_gemm<false, false, true><<<gQKV, 256>>>(af, wf + WQ_OFF, 10, SEG, bqkv, nullptr, nullptr, qkv, N_ROWS, 3 * D_MODEL, D_MODEL);
    attn_tc_kernel<<<gAtt, 128>>>(qkv, qkv + D_MODEL, qkv + 2 * D_MODEL, af,
                                  3 * D_MODEL, 3 * D_MODEL, 1);
    tc_gemm<false, true, false><<<gD, 256>>>(af, wf + WO_OFF, 10, SEG, Bv[3], x, x1, nullptr, N_ROWS, D_MODEL, D_MODEL);

    // ---- cross-attention block (fused KV) ----
    ln_f16_kernel<<<N_ROWS, 256>>>(x1, ln2_g, ln2_b, af);
    tc_gemm<false, false, true><<<gD, 256>>>(af, wf + CQ_OFF, 10, SEG, Bv[4], nullptr, nullptr, ff, N_ROWS, D_MODEL, D_MODEL);
    tc_gemm<false, false, true><<<gKV, 256>>>(sf, wf + CK_OFF, 10, SEG, bkv, nullptr, nullptr, qkv, N_ROWS, 2 * D_MODEL, D_MODEL);
    attn_tc_kernel<<<gAtt, 128>>>(ff, qkv, qkv + D_MODEL, af,
                                  D_MODEL, 2 * D_MODEL, 0);
    tc_gemm<false, true, false><<<gD, 256>>>(af, wf + CO_OFF, 10, SEG, Bv[7], x1, x2, nullptr, N_ROWS, D_MODEL, D_MODEL);

    // ---- FFN block ----
    ln_f16_kernel<<<N_ROWS, 256>>>(x2, ln3_g, ln3_b, af);
    tc_gemm<true, false, true><<<gF1, 256>>>(af, wf + W1_OFF, 12, SEG, ff_b1, nullptr, nullptr, ff, N_ROWS, DFF_, D_MODEL);
    tc_gemm<false, true, false><<<gD, 256>>>(ff, wf + W2_OFF, 10, SEG, ff_b2, x2, out, nullptr, N_ROWS, D_MODEL, DFF_);
}